// round 11
// baseline (speedup 1.0000x reference)
#include <cuda_runtime.h>
#include <math.h>

#define Bsz 32
#define Tlen 512
#define Hd 512

// ---------------- scratch (static device globals per harness rules) ----------
__device__ float g_xg0[(size_t)Bsz * Tlen * 4 * Hd];   // 134 MB  (dir 0 gates)
__device__ float g_xg1[(size_t)Bsz * Tlen * 4 * Hd];   // 134 MB  (dir 1 gates)
__device__ float g_x1[(size_t)Bsz * Tlen * 2 * Hd];    // 64 MB   (layer-0 output)
__device__ unsigned int g_sync[4];                     // per-layer, per-dir barriers

// ---------------- tf32 helpers ------------------------------------------------
__device__ __forceinline__ float tf32_round(float v) {
    unsigned r;
    asm("cvt.rna.tf32.f32 %0, %1;" : "=r"(r) : "f"(v));
    return __uint_as_float(r);
}
__device__ __forceinline__ void mma_tf32(float* c, const unsigned* a, const unsigned* b) {
    asm volatile(
        "mma.sync.aligned.m16n8k8.row.col.f32.tf32.tf32.f32 "
        "{%0,%1,%2,%3}, {%4,%5,%6,%7}, {%8,%9}, {%0,%1,%2,%3};"
        : "+f"(c[0]), "+f"(c[1]), "+f"(c[2]), "+f"(c[3])
        : "r"(a[0]), "r"(a[1]), "r"(a[2]), "r"(a[3]), "r"(b[0]), "r"(b[1]));
}

// ---------------- TF32 2-term split GEMM: C = A*W^T + bias --------------------
#define HSTR 12
#define TILE_F (2 * 128 * HSTR)
#define BUF_F  (3 * TILE_F)
#define GEMM_SMEM (2 * BUF_F * 4)

__global__ __launch_bounds__(256) void tf32_gemm_bias(
    const float* __restrict__ A, const float* __restrict__ W,
    const float* __restrict__ bias, float* __restrict__ C,
    int M, int N, int K)
{
    extern __shared__ float sm[];
    const int tid  = threadIdx.x;
    const int lane = tid & 31;
    const int warp = tid >> 5;
    const int gid  = lane >> 2;
    const int tig  = lane & 3;
    const int bx = blockIdx.x, by = blockIdx.y;
    const int mo = (warp >> 2) * 64;
    const int no = (warp & 3) * 32;

    const int lrow = tid >> 2;
    const int lkq  = (tid & 3) << 2;
    const int lhalf = lkq >> 3;
    const int lkoff = lkq & 7;

    const float* Ag0 = A + (size_t)(by * 128 + lrow) * K + lkq;
    const float* Ag1 = A + (size_t)(by * 128 + lrow + 64) * K + lkq;
    const float* Wg0 = W + (size_t)(bx * 128 + lrow) * K + lkq;
    const float* Wg1 = W + (size_t)(bx * 128 + lrow + 64) * K + lkq;

    float c[4][4][4];
#pragma unroll
    for (int mt = 0; mt < 4; mt++)
#pragma unroll
        for (int nt = 0; nt < 4; nt++)
#pragma unroll
            for (int i = 0; i < 4; i++) c[mt][nt][i] = 0.f;

    const int nk = K >> 4;
    float4 ra0, ra1, rb0, rb1;

    ra0 = *(const float4*)Ag0; ra1 = *(const float4*)Ag1;
    rb0 = *(const float4*)Wg0; rb1 = *(const float4*)Wg1;

    auto sts_a = [&](int p, float4 v, int row) {
        float* dst = sm + p * BUF_F + lhalf * 1536 + row * HSTR + lkoff;
        float4 hv;
        hv.x = tf32_round(v.x); hv.y = tf32_round(v.y);
        hv.z = tf32_round(v.z); hv.w = tf32_round(v.w);
        *(float4*)dst = hv;
    };
    auto sts_b = [&](int p, float4 v, int row) {
        float* dst_h = sm + p * BUF_F + TILE_F + lhalf * 1536 + row * HSTR + lkoff;
        float4 hv, lv;
        hv.x = tf32_round(v.x); lv.x = tf32_round(v.x - hv.x);
        hv.y = tf32_round(v.y); lv.y = tf32_round(v.y - hv.y);
        hv.z = tf32_round(v.z); lv.z = tf32_round(v.z - hv.z);
        hv.w = tf32_round(v.w); lv.w = tf32_round(v.w - hv.w);
        *(float4*)dst_h = hv;
        *(float4*)(dst_h + TILE_F) = lv;
    };

    sts_a(0, ra0, lrow);
    sts_a(0, ra1, lrow + 64);
    sts_b(0, rb0, lrow);
    sts_b(0, rb1, lrow + 64);
    __syncthreads();

    int p = 0;
    for (int kt = 0; kt < nk; ++kt) {
        if (kt + 1 < nk) {
            const int k0 = (kt + 1) << 4;
            ra0 = *(const float4*)(Ag0 + k0); ra1 = *(const float4*)(Ag1 + k0);
            rb0 = *(const float4*)(Wg0 + k0); rb1 = *(const float4*)(Wg1 + k0);
        }

#pragma unroll
        for (int h = 0; h < 2; ++h) {
            const float* sA_h = sm + p * BUF_F + h * 1536;
            const float* sB_h = sA_h + TILE_F;
            const float* sB_l = sA_h + 2 * TILE_F;

            unsigned ah[4][4], bh[4][2], bl[4][2];
#pragma unroll
            for (int mt = 0; mt < 4; mt++) {
                int r0 = (mo + mt * 16 + gid) * HSTR + tig;
                ah[mt][0] = __float_as_uint(sA_h[r0]);
                ah[mt][1] = __float_as_uint(sA_h[r0 + 8 * HSTR]);
                ah[mt][2] = __float_as_uint(sA_h[r0 + 4]);
                ah[mt][3] = __float_as_uint(sA_h[r0 + 8 * HSTR + 4]);
            }
#pragma unroll
            for (int nt = 0; nt < 4; nt++) {
                int n0 = (no + nt * 8 + gid) * HSTR + tig;
                bh[nt][0] = __float_as_uint(sB_h[n0]);
                bh[nt][1] = __float_as_uint(sB_h[n0 + 4]);
                bl[nt][0] = __float_as_uint(sB_l[n0]);
                bl[nt][1] = __float_as_uint(sB_l[n0 + 4]);
            }
#pragma unroll
            for (int mt = 0; mt < 4; mt++)
#pragma unroll
                for (int nt = 0; nt < 4; nt++) {
                    mma_tf32(c[mt][nt], ah[mt], bh[nt]);
                    mma_tf32(c[mt][nt], ah[mt], bl[nt]);
                }
        }

        if (kt + 1 < nk) {
            sts_a(1 - p, ra0, lrow);
            sts_a(1 - p, ra1, lrow + 64);
            sts_b(1 - p, rb0, lrow);
            sts_b(1 - p, rb1, lrow + 64);
        }
        __syncthreads();
        p ^= 1;
    }

#pragma unroll
    for (int nt = 0; nt < 4; nt++) {
        int col = bx * 128 + no + nt * 8 + tig * 2;
        float bv0 = bias[col], bv1 = bias[col + 1];
#pragma unroll
        for (int mt = 0; mt < 4; mt++) {
            int row0 = by * 128 + mo + mt * 16 + gid;
            float2 v0 = make_float2(c[mt][nt][0] + bv0, c[mt][nt][1] + bv1);
            float2 v1 = make_float2(c[mt][nt][2] + bv0, c[mt][nt][3] + bv1);
            *(float2*)(C + (size_t)row0 * N + col) = v0;
            *(float2*)(C + (size_t)(row0 + 8) * N + col) = v1;
        }
    }
}

// ---------------- grid barrier helpers ---------------------------------------
__device__ __forceinline__ unsigned int ld_acq(const unsigned int* p) {
    unsigned int v;
    asm volatile("ld.acquire.gpu.global.u32 %0, [%1];" : "=r"(v) : "l"(p));
    return v;
}
__device__ __forceinline__ void grid_sync(unsigned int* cnt, unsigned int target) {
    __syncthreads();
    if (threadIdx.x == 0) {
        asm volatile("red.release.gpu.global.add.u32 [%0], %1;" :: "l"(cnt), "r"(1u));
        unsigned int guard = 0;
        while (ld_acq(cnt) < target) {
            __nanosleep(32);
            if (++guard > 30000000u) break;
        }
    }
    __syncthreads();
}

__global__ void reset_sync(unsigned int* p) { p[0] = 0; p[1] = 0; p[2] = 0; p[3] = 0; }

// ---------------- persistent bidirectional LSTM recurrence --------------------
// Register-weight matvec (kills the 4096 weight-broadcast wavefronts/CTA/step):
// grid (64,2), 256 thr, warp = unit j. Compute mapping: lane = (gate=lane&3,
// kp=lane>>2); each lane holds Whh[gate*512+j, kp*64 .. +63] in 16 float4 regs
// (loaded once from gmem). h staged [b][k] pitch 544 (+4 pad per 64-chunk):
// compute LDS.128 is warp-uniform in b -> 8 distinct 16B chunks x 4-gate
// broadcast = 1 conflict-free wavefront, 128B useful. Per b: 64 FFMA into 4
// accs, 3 shfl.xor reduce over kp, 4 shfl broadcasts; lane==b keeps its gates.
// Epilogue/xg/store/avg use lane = b (same as R10). Bounded-spin per-dir
// barrier unchanged. smem = 32*544*4 = 69632 B; 1 CTA/SM, 128 CTAs wave-1.
#define HPITCH 544
#define LSTM_SMEM (Bsz * HPITCH * 4)

__device__ __forceinline__ float sigmoidf(float x) { return 1.f / (1.f + expf(-x)); }

__global__ __launch_bounds__(256) void lstm_persist(
    const float* __restrict__ xg0, const float* __restrict__ xg1,
    const float* __restrict__ Whh0, const float* __restrict__ Whh1,
    float* __restrict__ seq,   // [B*T, 1024]: fwd cols 0..511, bwd 512..1023
    float* __restrict__ avg,   // [B, 1024] or nullptr
    unsigned int* __restrict__ sync_base)
{
    extern __shared__ float hs[];     // 32 * 544 floats

    const int tid  = threadIdx.x;
    const int dir  = blockIdx.y;
    const int lane = tid & 31;
    const int warp = tid >> 5;
    const int gate = lane & 3;        // 0=i 1=f 2=g 3=o
    const int kp   = lane >> 2;       // 0..7
    const int jbase = blockIdx.x << 3;
    const int j    = jbase + warp;
    unsigned int* sync_cnt = sync_base + dir;

    // one-time weight slice into registers (row = gate*512 + j, cols kp*64..+63)
    const float* whh = dir ? Whh1 : Whh0;
    float4 wreg[16];
    {
        const float4* wb = (const float4*)(whh + ((size_t)(gate * 512 + j)) * 512 + kp * 64);
#pragma unroll
        for (int i = 0; i < 16; ++i) wreg[i] = wb[i];
    }

    const float* xg = dir ? xg1 : xg0;
    const unsigned int nb = gridDim.x;          // 64 CTAs per direction
    unsigned int target = 0;
    float c = 0.f;
    float hsum = 0.f;

    // xg prefetch for step 0 (lane = b)
    float pxi, pxf, pxg, pxo;
    {
        int t0 = dir ? (Tlen - 1) : 0;
        int bs = (lane * Tlen + t0) * 2048;
        pxi = xg[bs + j];        pxf = xg[bs + 512 + j];
        pxg = xg[bs + 1024 + j]; pxo = xg[bs + 1536 + j];
    }

    for (int s = 0; s < Tlen; ++s) {
        const int tcur = dir ? (Tlen - 1 - s) : s;

        if (s == 0) {
            for (int i = tid; i < Bsz * HPITCH; i += 256) hs[i] = 0.f;
        } else {
            const int tprev = dir ? (tcur + 1) : (tcur - 1);
            const int lb  = tid >> 3;            // 0..31 batch
            const int klo = (tid & 7) << 2;      // 0,4,...,28
            const float* hp = seq + (size_t)(lb * Tlen + tprev) * 1024 + dir * 512;
#pragma unroll
            for (int it = 0; it < 16; ++it) {
                int k = klo + (it << 5);         // < 512
                float4 v = *(const float4*)(hp + k);
                *(float4*)&hs[lb * HPITCH + ((k >> 6) * 68) + (k & 63)] = v;
            }
        }
        __syncthreads();

        // per-b matvec: lane computes partial over its (gate, 64-k slice)
        float ri = 0.f, rf = 0.f, rg = 0.f, ro = 0.f;
        for (int b0 = 0; b0 < Bsz; ++b0) {
            const float4* hp4 = (const float4*)(hs + b0 * HPITCH + kp * 68);
            float a0 = 0.f, a1 = 0.f, a2 = 0.f, a3 = 0.f;
#pragma unroll
            for (int i = 0; i < 16; i += 4) {
                float4 h0 = hp4[i], h1 = hp4[i + 1], h2 = hp4[i + 2], h3 = hp4[i + 3];
                a0 = __fmaf_rn(wreg[i].x, h0.x, a0);
                a0 = __fmaf_rn(wreg[i].y, h0.y, a0);
                a0 = __fmaf_rn(wreg[i].z, h0.z, a0);
                a0 = __fmaf_rn(wreg[i].w, h0.w, a0);
                a1 = __fmaf_rn(wreg[i + 1].x, h1.x, a1);
                a1 = __fmaf_rn(wreg[i + 1].y, h1.y, a1);
                a1 = __fmaf_rn(wreg[i + 1].z, h1.z, a1);
                a1 = __fmaf_rn(wreg[i + 1].w, h1.w, a1);
                a2 = __fmaf_rn(wreg[i + 2].x, h2.x, a2);
                a2 = __fmaf_rn(wreg[i + 2].y, h2.y, a2);
                a2 = __fmaf_rn(wreg[i + 2].z, h2.z, a2);
                a2 = __fmaf_rn(wreg[i + 2].w, h2.w, a2);
                a3 = __fmaf_rn(wreg[i + 3].x, h3.x, a3);
                a3 = __fmaf_rn(wreg[i + 3].y, h3.y, a3);
                a3 = __fmaf_rn(wreg[i + 3].z, h3.z, a3);
                a3 = __fmaf_rn(wreg[i + 3].w, h3.w, a3);
            }
            float v = (a0 + a1) + (a2 + a3);
            // reduce over kp (lane bits 2..4)
            v += __shfl_xor_sync(0xffffffffu, v, 4);
            v += __shfl_xor_sync(0xffffffffu, v, 8);
            v += __shfl_xor_sync(0xffffffffu, v, 16);
            // lanes 0..3 hold the 4 gate totals for b0; broadcast, lane==b0 keeps
            float s0 = __shfl_sync(0xffffffffu, v, 0);
            float s1 = __shfl_sync(0xffffffffu, v, 1);
            float s2 = __shfl_sync(0xffffffffu, v, 2);
            float s3 = __shfl_sync(0xffffffffu, v, 3);
            if (lane == b0) { ri = s0; rf = s1; rg = s2; ro = s3; }
        }

        // epilogue: lane = b
        float gi = ri + pxi;
        float gf = rf + pxf;
        float gg = rg + pxg;
        float go = ro + pxo;
        c = sigmoidf(gf) * c + sigmoidf(gi) * tanhf(gg);
        float h = sigmoidf(go) * tanhf(c);
        seq[(size_t)(lane * Tlen + tcur) * 1024 + dir * 512 + j] = h;
        hsum += h;

        if (s + 1 < Tlen) {
            // prefetch next step's xg before the barrier (hidden by the spin)
            int tn = dir ? (tcur - 1) : (tcur + 1);
            int bs = (lane * Tlen + tn) * 2048;
            pxi = xg[bs + j];        pxf = xg[bs + 512 + j];
            pxg = xg[bs + 1024 + j]; pxo = xg[bs + 1536 + j];

            target += nb;
            grid_sync(sync_cnt, target);   // also guards hs overwrite next step
        }
    }

    if (avg) avg[lane * 1024 + dir * 512 + j] = hsum * (1.f / Tlen);
}

// ---------------- launch ------------------------------------------------------
extern "C" void kernel_launch(void* const* d_in, const int* in_sizes, int n_in,
                              void* d_out, int out_size)
{
    const float* x     = (const float*)d_in[0];
    const float* Wih0f = (const float*)d_in[1];
    const float* Whh0f = (const float*)d_in[2];
    const float* b0f   = (const float*)d_in[3];
    const float* Wih0b = (const float*)d_in[4];
    const float* Whh0b = (const float*)d_in[5];
    const float* b0b   = (const float*)d_in[6];
    const float* Wih1f = (const float*)d_in[7];
    const float* Whh1f = (const float*)d_in[8];
    const float* b1f   = (const float*)d_in[9];
    const float* Wih1b = (const float*)d_in[10];
    const float* Whh1b = (const float*)d_in[11];
    const float* b1b   = (const float*)d_in[12];

    float* avg    = (float*)d_out;
    float* outseq = avg + Bsz * 2 * Hd;   // avg_out first, then out [B,T,1024]

    float *xg0, *xg1, *x1;
    unsigned int* syncp;
    cudaGetSymbolAddress((void**)&xg0, g_xg0);
    cudaGetSymbolAddress((void**)&xg1, g_xg1);
    cudaGetSymbolAddress((void**)&x1,  g_x1);
    cudaGetSymbolAddress((void**)&syncp, g_sync);

    cudaFuncSetAttribute(lstm_persist, cudaFuncAttributeMaxDynamicSharedMemorySize, LSTM_SMEM);
    cudaFuncSetAttribute(tf32_gemm_bias, cudaFuncAttributeMaxDynamicSharedMemorySize, GEMM_SMEM);

    dim3 gemm_grid(2048 / 128, 16384 / 128);     // (16, 128)
    dim3 step_grid(64, 2);

    reset_sync<<<1, 1>>>(syncp);

    // Layer 0 input gates (tensor cores, tf32 2-term split)
    tf32_gemm_bias<<<gemm_grid, 256, GEMM_SMEM>>>(x, Wih0f, b0f, xg0, 16384, 2048, 512);
    tf32_gemm_bias<<<gemm_grid, 256, GEMM_SMEM>>>(x, Wih0b, b0b, xg1, 16384, 2048, 512);
    // Layer 0 recurrence (persistent, per-dir grid-sync: counters 0,1)
    lstm_persist<<<step_grid, 256, LSTM_SMEM>>>(xg0, xg1, Whh0f, Whh0b, x1, nullptr, syncp);
    // Layer 1 input gates (K = 1024)
    tf32_gemm_bias<<<gemm_grid, 256, GEMM_SMEM>>>(x1, Wih1f, b1f, xg0, 16384, 2048, 1024);
    tf32_gemm_bias<<<gemm_grid, 256, GEMM_SMEM>>>(x1, Wih1b, b1b, xg1, 16384, 2048, 1024);
    // Layer 1 recurrence -> out region of d_out, mean fused (counters 2,3)
    lstm_persist<<<step_grid, 256, LSTM_SMEM>>>(xg0, xg1, Whh1f, Whh1b, outseq, avg, syncp + 2);
}

// round 12
// speedup vs baseline: 1.2575x; 1.2575x over previous
#include <cuda_runtime.h>
#include <math.h>

#define Bsz 32
#define Tlen 512
#define Hd 512

// ---------------- scratch (static device globals per harness rules) ----------
__device__ float g_xg0[(size_t)Bsz * Tlen * 4 * Hd];   // 134 MB  (dir 0 gates)
__device__ float g_xg1[(size_t)Bsz * Tlen * 4 * Hd];   // 134 MB  (dir 1 gates)
__device__ float g_x1[(size_t)Bsz * Tlen * 2 * Hd];    // 64 MB   (layer-0 output)
__device__ unsigned int g_sync[4];                     // per-layer, per-dir barriers

// ---------------- tf32 helpers ------------------------------------------------
__device__ __forceinline__ float tf32_round(float v) {
    unsigned r;
    asm("cvt.rna.tf32.f32 %0, %1;" : "=r"(r) : "f"(v));
    return __uint_as_float(r);
}
__device__ __forceinline__ void mma_tf32(float* c, const unsigned* a, const unsigned* b) {
    asm volatile(
        "mma.sync.aligned.m16n8k8.row.col.f32.tf32.tf32.f32 "
        "{%0,%1,%2,%3}, {%4,%5,%6,%7}, {%8,%9}, {%0,%1,%2,%3};"
        : "+f"(c[0]), "+f"(c[1]), "+f"(c[2]), "+f"(c[3])
        : "r"(a[0]), "r"(a[1]), "r"(a[2]), "r"(a[3]), "r"(b[0]), "r"(b[1]));
}

// ---------------- TF32 2-term split GEMM: C = A*W^T + bias --------------------
#define HSTR 12
#define TILE_F (2 * 128 * HSTR)
#define BUF_F  (3 * TILE_F)
#define GEMM_SMEM (2 * BUF_F * 4)

__global__ __launch_bounds__(256) void tf32_gemm_bias(
    const float* __restrict__ A, const float* __restrict__ W,
    const float* __restrict__ bias, float* __restrict__ C,
    int M, int N, int K)
{
    extern __shared__ float sm[];
    const int tid  = threadIdx.x;
    const int lane = tid & 31;
    const int warp = tid >> 5;
    const int gid  = lane >> 2;
    const int tig  = lane & 3;
    const int bx = blockIdx.x, by = blockIdx.y;
    const int mo = (warp >> 2) * 64;
    const int no = (warp & 3) * 32;

    const int lrow = tid >> 2;
    const int lkq  = (tid & 3) << 2;
    const int lhalf = lkq >> 3;
    const int lkoff = lkq & 7;

    const float* Ag0 = A + (size_t)(by * 128 + lrow) * K + lkq;
    const float* Ag1 = A + (size_t)(by * 128 + lrow + 64) * K + lkq;
    const float* Wg0 = W + (size_t)(bx * 128 + lrow) * K + lkq;
    const float* Wg1 = W + (size_t)(bx * 128 + lrow + 64) * K + lkq;

    float c[4][4][4];
#pragma unroll
    for (int mt = 0; mt < 4; mt++)
#pragma unroll
        for (int nt = 0; nt < 4; nt++)
#pragma unroll
            for (int i = 0; i < 4; i++) c[mt][nt][i] = 0.f;

    const int nk = K >> 4;
    float4 ra0, ra1, rb0, rb1;

    ra0 = *(const float4*)Ag0; ra1 = *(const float4*)Ag1;
    rb0 = *(const float4*)Wg0; rb1 = *(const float4*)Wg1;

    auto sts_a = [&](int p, float4 v, int row) {
        float* dst = sm + p * BUF_F + lhalf * 1536 + row * HSTR + lkoff;
        float4 hv;
        hv.x = tf32_round(v.x); hv.y = tf32_round(v.y);
        hv.z = tf32_round(v.z); hv.w = tf32_round(v.w);
        *(float4*)dst = hv;
    };
    auto sts_b = [&](int p, float4 v, int row) {
        float* dst_h = sm + p * BUF_F + TILE_F + lhalf * 1536 + row * HSTR + lkoff;
        float4 hv, lv;
        hv.x = tf32_round(v.x); lv.x = tf32_round(v.x - hv.x);
        hv.y = tf32_round(v.y); lv.y = tf32_round(v.y - hv.y);
        hv.z = tf32_round(v.z); lv.z = tf32_round(v.z - hv.z);
        hv.w = tf32_round(v.w); lv.w = tf32_round(v.w - hv.w);
        *(float4*)dst_h = hv;
        *(float4*)(dst_h + TILE_F) = lv;
    };

    sts_a(0, ra0, lrow);
    sts_a(0, ra1, lrow + 64);
    sts_b(0, rb0, lrow);
    sts_b(0, rb1, lrow + 64);
    __syncthreads();

    int p = 0;
    for (int kt = 0; kt < nk; ++kt) {
        if (kt + 1 < nk) {
            const int k0 = (kt + 1) << 4;
            ra0 = *(const float4*)(Ag0 + k0); ra1 = *(const float4*)(Ag1 + k0);
            rb0 = *(const float4*)(Wg0 + k0); rb1 = *(const float4*)(Wg1 + k0);
        }

#pragma unroll
        for (int h = 0; h < 2; ++h) {
            const float* sA_h = sm + p * BUF_F + h * 1536;
            const float* sB_h = sA_h + TILE_F;
            const float* sB_l = sA_h + 2 * TILE_F;

            unsigned ah[4][4], bh[4][2], bl[4][2];
#pragma unroll
            for (int mt = 0; mt < 4; mt++) {
                int r0 = (mo + mt * 16 + gid) * HSTR + tig;
                ah[mt][0] = __float_as_uint(sA_h[r0]);
                ah[mt][1] = __float_as_uint(sA_h[r0 + 8 * HSTR]);
                ah[mt][2] = __float_as_uint(sA_h[r0 + 4]);
                ah[mt][3] = __float_as_uint(sA_h[r0 + 8 * HSTR + 4]);
            }
#pragma unroll
            for (int nt = 0; nt < 4; nt++) {
                int n0 = (no + nt * 8 + gid) * HSTR + tig;
                bh[nt][0] = __float_as_uint(sB_h[n0]);
                bh[nt][1] = __float_as_uint(sB_h[n0 + 4]);
                bl[nt][0] = __float_as_uint(sB_l[n0]);
                bl[nt][1] = __float_as_uint(sB_l[n0 + 4]);
            }
#pragma unroll
            for (int mt = 0; mt < 4; mt++)
#pragma unroll
                for (int nt = 0; nt < 4; nt++) {
                    mma_tf32(c[mt][nt], ah[mt], bh[nt]);
                    mma_tf32(c[mt][nt], ah[mt], bl[nt]);
                }
        }

        if (kt + 1 < nk) {
            sts_a(1 - p, ra0, lrow);
            sts_a(1 - p, ra1, lrow + 64);
            sts_b(1 - p, rb0, lrow);
            sts_b(1 - p, rb1, lrow + 64);
        }
        __syncthreads();
        p ^= 1;
    }

#pragma unroll
    for (int nt = 0; nt < 4; nt++) {
        int col = bx * 128 + no + nt * 8 + tig * 2;
        float bv0 = bias[col], bv1 = bias[col + 1];
#pragma unroll
        for (int mt = 0; mt < 4; mt++) {
            int row0 = by * 128 + mo + mt * 16 + gid;
            float2 v0 = make_float2(c[mt][nt][0] + bv0, c[mt][nt][1] + bv1);
            float2 v1 = make_float2(c[mt][nt][2] + bv0, c[mt][nt][3] + bv1);
            *(float2*)(C + (size_t)row0 * N + col) = v0;
            *(float2*)(C + (size_t)(row0 + 8) * N + col) = v1;
        }
    }
}

// ---------------- grid barrier helpers ---------------------------------------
__device__ __forceinline__ unsigned int ld_acq(const unsigned int* p) {
    unsigned int v;
    asm volatile("ld.acquire.gpu.global.u32 %0, [%1];" : "=r"(v) : "l"(p));
    return v;
}
__device__ __forceinline__ void grid_sync(unsigned int* cnt, unsigned int target) {
    __syncthreads();
    if (threadIdx.x == 0) {
        asm volatile("red.release.gpu.global.add.u32 [%0], %1;" :: "l"(cnt), "r"(1u));
        unsigned int guard = 0;
        while (ld_acq(cnt) < target) {
            __nanosleep(32);
            if (++guard > 30000000u) break;
        }
    }
    __syncthreads();
}

__global__ void reset_sync(unsigned int* p) { p[0] = 0; p[1] = 0; p[2] = 0; p[3] = 0; }

// ---------------- persistent bidirectional LSTM recurrence --------------------
// K-SPLIT, scalar FFMA only (no f32x2). 512 threads: warp w = 0..15,
// unit j = jbase + (w&7), khalf = w>>3 (k<256 / k>=256). Inner body identical
// pattern to R10 (hs [k][b] pitch 33, warp-uniform float4 weight LDS = 1-wf
// broadcast, dual accumulators per gate) but each warp covers 64 k4 instead of
// 128 -> per-warp issue work halves, 4 warps/SMSP hide LDS latency.
// khalf=1 writes partials to smem (1024 floats); khalf=0 combines + epilogue.
// smem: ws 16384 + hs 16896 + part 1024 = 34304 floats = 137216 B -> 1 CTA/SM,
// 128 CTAs <= 148 SMs wave-1 resident; bounded-spin per-dir barrier unchanged.
#define LSTM_SMEM ((16384 + 16896 + 1024) * 4)

__device__ __forceinline__ float sigmoidf(float x) { return 1.f / (1.f + expf(-x)); }

__global__ __launch_bounds__(512) void lstm_persist(
    const float* __restrict__ xg0, const float* __restrict__ xg1,
    const float* __restrict__ Whh0, const float* __restrict__ Whh1,
    float* __restrict__ seq,   // [B*T, 1024]: fwd cols 0..511, bwd 512..1023
    float* __restrict__ avg,   // [B, 1024] or nullptr
    unsigned int* __restrict__ sync_base)
{
    extern __shared__ float smem[];
    float* ws   = smem;                 // 16384 floats (weights, R10 layout)
    float* hs   = smem + 16384;         // 512*33 floats (h staging, R10 layout)
    float* part = smem + 33280;         // 1024 floats (khalf-1 partials)

    const int tid   = threadIdx.x;
    const int dir   = blockIdx.y;
    const int b     = tid & 31;         // lane = batch
    const int warp  = tid >> 5;         // 0..15
    const int w8    = warp & 7;         // unit within CTA
    const int khalf = warp >> 3;        // 0: k<256, 1: k>=256
    const int jbase = blockIdx.x << 3;
    const int j     = jbase + w8;
    unsigned int* sync_cnt = sync_base + dir;

    // Whh rows into SMEM (same layout as R10): row r = j_local*4 + gate
    const float* whh = dir ? Whh1 : Whh0;
    for (int i = tid; i < 4096; i += 512) {
        int r  = i >> 7;
        int k4 = i & 127;
        int j_local = r >> 2, gate = r & 3;
        ((float4*)ws)[r * 128 + k4] =
            ((const float4*)(whh + (size_t)(gate * 512 + jbase + j_local) * 512))[k4];
    }

    // weight pointers pre-offset to this warp's k-half (64 float4 each)
    const float4* wi = (const float4*)(ws + (w8 * 4 + 0) * 512 + khalf * 256);
    const float4* wf = (const float4*)(ws + (w8 * 4 + 1) * 512 + khalf * 256);
    const float4* wg = (const float4*)(ws + (w8 * 4 + 2) * 512 + khalf * 256);
    const float4* wo = (const float4*)(ws + (w8 * 4 + 3) * 512 + khalf * 256);
    const int kbase = khalf << 8;       // k offset (0 or 256)

    const float* xg = dir ? xg1 : xg0;
    const unsigned int nb = gridDim.x;  // 64 CTAs per direction
    unsigned int target = 0;
    float c = 0.f;
    float hsum = 0.f;

    // xg prefetch for step 0 (khalf 0 only; lane = b)
    float pxi = 0.f, pxf = 0.f, pxg = 0.f, pxo = 0.f;
    if (khalf == 0) {
        int t0 = dir ? (Tlen - 1) : 0;
        int bs = (b * Tlen + t0) * 2048;
        pxi = xg[bs + j];        pxf = xg[bs + 512 + j];
        pxg = xg[bs + 1024 + j]; pxo = xg[bs + 1536 + j];
    }

    for (int s = 0; s < Tlen; ++s) {
        const int tcur = dir ? (Tlen - 1 - s) : s;

        if (s == 0) {
            for (int i = tid; i < 512 * 33; i += 512) hs[i] = 0.f;
        } else {
            const int tprev = dir ? (tcur + 1) : (tcur - 1);
            const int lb  = tid >> 4;            // 0..31 batch
            const int klo = (tid & 15) << 2;     // 0..60
            const float* hp = seq + (size_t)(lb * Tlen + tprev) * 1024 + dir * 512;
#pragma unroll
            for (int it = 0; it < 8; ++it) {
                int k = klo + (it << 6);         // < 512
                float4 v = *(const float4*)(hp + k);
                hs[(k + 0) * 33 + lb] = v.x;
                hs[(k + 1) * 33 + lb] = v.y;
                hs[(k + 2) * 33 + lb] = v.z;
                hs[(k + 3) * 33 + lb] = v.w;
            }
        }
        __syncthreads();

        // dual accumulators per gate over this warp's 64 k4 (R10 body pattern)
        float ai = 0.f, af = 0.f, ag = 0.f, ao = 0.f;
        float aib = 0.f, afb = 0.f, agb = 0.f, aob = 0.f;
#pragma unroll 4
        for (int k4 = 0; k4 < 64; k4 += 2) {
            {
                float4 vi = wi[k4], vf = wf[k4], vg = wg[k4], vo = wo[k4];
                int kb = kbase + (k4 << 2);
                float h0 = hs[(kb + 0) * 33 + b];
                float h1 = hs[(kb + 1) * 33 + b];
                float h2 = hs[(kb + 2) * 33 + b];
                float h3 = hs[(kb + 3) * 33 + b];
                ai += vi.x * h0; ai += vi.y * h1; ai += vi.z * h2; ai += vi.w * h3;
                af += vf.x * h0; af += vf.y * h1; af += vf.z * h2; af += vf.w * h3;
                ag += vg.x * h0; ag += vg.y * h1; ag += vg.z * h2; ag += vg.w * h3;
                ao += vo.x * h0; ao += vo.y * h1; ao += vo.z * h2; ao += vo.w * h3;
            }
            {
                float4 vi = wi[k4 + 1], vf = wf[k4 + 1], vg = wg[k4 + 1], vo = wo[k4 + 1];
                int kb = kbase + ((k4 + 1) << 2);
                float h0 = hs[(kb + 0) * 33 + b];
                float h1 = hs[(kb + 1) * 33 + b];
                float h2 = hs[(kb + 2) * 33 + b];
                float h3 = hs[(kb + 3) * 33 + b];
                aib += vi.x * h0; aib += vi.y * h1; aib += vi.z * h2; aib += vi.w * h3;
                afb += vf.x * h0; afb += vf.y * h1; afb += vf.z * h2; afb += vf.w * h3;
                agb += vg.x * h0; agb += vg.y * h1; agb += vg.z * h2; agb += vg.w * h3;
                aob += vo.x * h0; aob += vo.y * h1; aob += vo.z * h2; aob += vo.w * h3;
            }
        }

        if (khalf == 1) {
            part[w8 * 128 +   0 + b] = ai + aib;
            part[w8 * 128 +  32 + b] = af + afb;
            part[w8 * 128 +  64 + b] = ag + agb;
            part[w8 * 128 +  96 + b] = ao + aob;
        }
        __syncthreads();

        if (khalf == 0) {
            float gi = (ai + aib) + part[w8 * 128 +   0 + b] + pxi;
            float gf = (af + afb) + part[w8 * 128 +  32 + b] + pxf;
            float gg = (ag + agb) + part[w8 * 128 +  64 + b] + pxg;
            float go = (ao + aob) + part[w8 * 128 +  96 + b] + pxo;

            c = sigmoidf(gf) * c + sigmoidf(gi) * tanhf(gg);
            float h = sigmoidf(go) * tanhf(c);
            seq[(size_t)(b * Tlen + tcur) * 1024 + dir * 512 + j] = h;
            hsum += h;
        }

        if (s + 1 < Tlen) {
            // prefetch next step's xg before the barrier (hidden by the spin)
            if (khalf == 0) {
                int tn = dir ? (tcur - 1) : (tcur + 1);
                int bs = (b * Tlen + tn) * 2048;
                pxi = xg[bs + j];        pxf = xg[bs + 512 + j];
                pxg = xg[bs + 1024 + j]; pxo = xg[bs + 1536 + j];
            }
            target += nb;
            grid_sync(sync_cnt, target);   // also guards hs/part overwrite
        }
    }

    if (avg && khalf == 0) avg[b * 1024 + dir * 512 + j] = hsum * (1.f / Tlen);
}

// ---------------- launch ------------------------------------------------------
extern "C" void kernel_launch(void* const* d_in, const int* in_sizes, int n_in,
                              void* d_out, int out_size)
{
    const float* x     = (const float*)d_in[0];
    const float* Wih0f = (const float*)d_in[1];
    const float* Whh0f = (const float*)d_in[2];
    const float* b0f   = (const float*)d_in[3];
    const float* Wih0b = (const float*)d_in[4];
    const float* Whh0b = (const float*)d_in[5];
    const float* b0b   = (const float*)d_in[6];
    const float* Wih1f = (const float*)d_in[7];
    const float* Whh1f = (const float*)d_in[8];
    const float* b1f   = (const float*)d_in[9];
    const float* Wih1b = (const float*)d_in[10];
    const float* Whh1b = (const float*)d_in[11];
    const float* b1b   = (const float*)d_in[12];

    float* avg    = (float*)d_out;
    float* outseq = avg + Bsz * 2 * Hd;   // avg_out first, then out [B,T,1024]

    float *xg0, *xg1, *x1;
    unsigned int* syncp;
    cudaGetSymbolAddress((void**)&xg0, g_xg0);
    cudaGetSymbolAddress((void**)&xg1, g_xg1);
    cudaGetSymbolAddress((void**)&x1,  g_x1);
    cudaGetSymbolAddress((void**)&syncp, g_sync);

    cudaFuncSetAttribute(lstm_persist, cudaFuncAttributeMaxDynamicSharedMemorySize, LSTM_SMEM);
    cudaFuncSetAttribute(tf32_gemm_bias, cudaFuncAttributeMaxDynamicSharedMemorySize, GEMM_SMEM);

    dim3 gemm_grid(2048 / 128, 16384 / 128);     // (16, 128)
    dim3 step_grid(64, 2);

    reset_sync<<<1, 1>>>(syncp);

    // Layer 0 input gates (tensor cores, tf32 2-term split)
    tf32_gemm_bias<<<gemm_grid, 256, GEMM_SMEM>>>(x, Wih0f, b0f, xg0, 16384, 2048, 512);
    tf32_gemm_bias<<<gemm_grid, 256, GEMM_SMEM>>>(x, Wih0b, b0b, xg1, 16384, 2048, 512);
    // Layer 0 recurrence (persistent, per-dir grid-sync: counters 0,1)
    lstm_persist<<<step_grid, 512, LSTM_SMEM>>>(xg0, xg1, Whh0f, Whh0b, x1, nullptr, syncp);
    // Layer 1 input gates (K = 1024)
    tf32_gemm_bias<<<gemm_grid, 256, GEMM_SMEM>>>(x1, Wih1f, b1f, xg0, 16384, 2048, 1024);
    tf32_gemm_bias<<<gemm_grid, 256, GEMM_SMEM>>>(x1, Wih1b, b1b, xg1, 16384, 2048, 1024);
    // Layer 1 recurrence -> out region of d_out, mean fused (counters 2,3)
    lstm_persist<<<step_grid, 512, LSTM_SMEM>>>(xg0, xg1, Whh1f, Whh1b, outseq, avg, syncp + 2);
}

// round 13
// speedup vs baseline: 1.4692x; 1.1684x over previous
#include <cuda_runtime.h>
#include <math.h>

#define Bsz 32
#define Tlen 512
#define Hd 512

// ---------------- scratch (static device globals per harness rules) ----------
__device__ float g_xg0[(size_t)Bsz * Tlen * 4 * Hd];   // 134 MB  (dir 0 gates)
__device__ float g_xg1[(size_t)Bsz * Tlen * 4 * Hd];   // 134 MB  (dir 1 gates)
__device__ float g_x1[(size_t)Bsz * Tlen * 2 * Hd];    // 64 MB   (layer-0 output)
__device__ unsigned int g_sync[4];                     // per-layer, per-dir barriers

// ---------------- tf32 helpers ------------------------------------------------
__device__ __forceinline__ float tf32_round(float v) {
    unsigned r;
    asm("cvt.rna.tf32.f32 %0, %1;" : "=r"(r) : "f"(v));
    return __uint_as_float(r);
}
__device__ __forceinline__ unsigned tf32_bits(float v) {
    unsigned r;
    asm("cvt.rna.tf32.f32 %0, %1;" : "=r"(r) : "f"(v));
    return r;
}
__device__ __forceinline__ void mma_tf32(float* c, const unsigned* a, const unsigned* b) {
    asm volatile(
        "mma.sync.aligned.m16n8k8.row.col.f32.tf32.tf32.f32 "
        "{%0,%1,%2,%3}, {%4,%5,%6,%7}, {%8,%9}, {%0,%1,%2,%3};"
        : "+f"(c[0]), "+f"(c[1]), "+f"(c[2]), "+f"(c[3])
        : "r"(a[0]), "r"(a[1]), "r"(a[2]), "r"(a[3]), "r"(b[0]), "r"(b[1]));
}

// ---------------- TF32 2-term split GEMM: C = A*W^T + bias --------------------
#define HSTR 12
#define TILE_F (2 * 128 * HSTR)
#define BUF_F  (3 * TILE_F)
#define GEMM_SMEM (2 * BUF_F * 4)

__global__ __launch_bounds__(256) void tf32_gemm_bias(
    const float* __restrict__ A, const float* __restrict__ W,
    const float* __restrict__ bias, float* __restrict__ C,
    int M, int N, int K)
{
    extern __shared__ float sm[];
    const int tid  = threadIdx.x;
    const int lane = tid & 31;
    const int warp = tid >> 5;
    const int gid  = lane >> 2;
    const int tig  = lane & 3;
    const int bx = blockIdx.x, by = blockIdx.y;
    const int mo = (warp >> 2) * 64;
    const int no = (warp & 3) * 32;

    const int lrow = tid >> 2;
    const int lkq  = (tid & 3) << 2;
    const int lhalf = lkq >> 3;
    const int lkoff = lkq & 7;

    const float* Ag0 = A + (size_t)(by * 128 + lrow) * K + lkq;
    const float* Ag1 = A + (size_t)(by * 128 + lrow + 64) * K + lkq;
    const float* Wg0 = W + (size_t)(bx * 128 + lrow) * K + lkq;
    const float* Wg1 = W + (size_t)(bx * 128 + lrow + 64) * K + lkq;

    float c[4][4][4];
#pragma unroll
    for (int mt = 0; mt < 4; mt++)
#pragma unroll
        for (int nt = 0; nt < 4; nt++)
#pragma unroll
            for (int i = 0; i < 4; i++) c[mt][nt][i] = 0.f;

    const int nk = K >> 4;
    float4 ra0, ra1, rb0, rb1;

    ra0 = *(const float4*)Ag0; ra1 = *(const float4*)Ag1;
    rb0 = *(const float4*)Wg0; rb1 = *(const float4*)Wg1;

    auto sts_a = [&](int p, float4 v, int row) {
        float* dst = sm + p * BUF_F + lhalf * 1536 + row * HSTR + lkoff;
        float4 hv;
        hv.x = tf32_round(v.x); hv.y = tf32_round(v.y);
        hv.z = tf32_round(v.z); hv.w = tf32_round(v.w);
        *(float4*)dst = hv;
    };
    auto sts_b = [&](int p, float4 v, int row) {
        float* dst_h = sm + p * BUF_F + TILE_F + lhalf * 1536 + row * HSTR + lkoff;
        float4 hv, lv;
        hv.x = tf32_round(v.x); lv.x = tf32_round(v.x - hv.x);
        hv.y = tf32_round(v.y); lv.y = tf32_round(v.y - hv.y);
        hv.z = tf32_round(v.z); lv.z = tf32_round(v.z - hv.z);
        hv.w = tf32_round(v.w); lv.w = tf32_round(v.w - hv.w);
        *(float4*)dst_h = hv;
        *(float4*)(dst_h + TILE_F) = lv;
    };

    sts_a(0, ra0, lrow);
    sts_a(0, ra1, lrow + 64);
    sts_b(0, rb0, lrow);
    sts_b(0, rb1, lrow + 64);
    __syncthreads();

    int p = 0;
    for (int kt = 0; kt < nk; ++kt) {
        if (kt + 1 < nk) {
            const int k0 = (kt + 1) << 4;
            ra0 = *(const float4*)(Ag0 + k0); ra1 = *(const float4*)(Ag1 + k0);
            rb0 = *(const float4*)(Wg0 + k0); rb1 = *(const float4*)(Wg1 + k0);
        }

#pragma unroll
        for (int h = 0; h < 2; ++h) {
            const float* sA_h = sm + p * BUF_F + h * 1536;
            const float* sB_h = sA_h + TILE_F;
            const float* sB_l = sA_h + 2 * TILE_F;

            unsigned ah[4][4], bh[4][2], bl[4][2];
#pragma unroll
            for (int mt = 0; mt < 4; mt++) {
                int r0 = (mo + mt * 16 + gid) * HSTR + tig;
                ah[mt][0] = __float_as_uint(sA_h[r0]);
                ah[mt][1] = __float_as_uint(sA_h[r0 + 8 * HSTR]);
                ah[mt][2] = __float_as_uint(sA_h[r0 + 4]);
                ah[mt][3] = __float_as_uint(sA_h[r0 + 8 * HSTR + 4]);
            }
#pragma unroll
            for (int nt = 0; nt < 4; nt++) {
                int n0 = (no + nt * 8 + gid) * HSTR + tig;
                bh[nt][0] = __float_as_uint(sB_h[n0]);
                bh[nt][1] = __float_as_uint(sB_h[n0 + 4]);
                bl[nt][0] = __float_as_uint(sB_l[n0]);
                bl[nt][1] = __float_as_uint(sB_l[n0 + 4]);
            }
#pragma unroll
            for (int mt = 0; mt < 4; mt++)
#pragma unroll
                for (int nt = 0; nt < 4; nt++) {
                    mma_tf32(c[mt][nt], ah[mt], bh[nt]);
                    mma_tf32(c[mt][nt], ah[mt], bl[nt]);
                }
        }

        if (kt + 1 < nk) {
            sts_a(1 - p, ra0, lrow);
            sts_a(1 - p, ra1, lrow + 64);
            sts_b(1 - p, rb0, lrow);
            sts_b(1 - p, rb1, lrow + 64);
        }
        __syncthreads();
        p ^= 1;
    }

#pragma unroll
    for (int nt = 0; nt < 4; nt++) {
        int col = bx * 128 + no + nt * 8 + tig * 2;
        float bv0 = bias[col], bv1 = bias[col + 1];
#pragma unroll
        for (int mt = 0; mt < 4; mt++) {
            int row0 = by * 128 + mo + mt * 16 + gid;
            float2 v0 = make_float2(c[mt][nt][0] + bv0, c[mt][nt][1] + bv1);
            float2 v1 = make_float2(c[mt][nt][2] + bv0, c[mt][nt][3] + bv1);
            *(float2*)(C + (size_t)row0 * N + col) = v0;
            *(float2*)(C + (size_t)(row0 + 8) * N + col) = v1;
        }
    }
}

// ---------------- grid barrier helpers ---------------------------------------
__device__ __forceinline__ unsigned int ld_acq(const unsigned int* p) {
    unsigned int v;
    asm volatile("ld.acquire.gpu.global.u32 %0, [%1];" : "=r"(v) : "l"(p));
    return v;
}
__device__ __forceinline__ void grid_sync(unsigned int* cnt, unsigned int target) {
    __syncthreads();
    if (threadIdx.x == 0) {
        asm volatile("red.release.gpu.global.add.u32 [%0], %1;" :: "l"(cnt), "r"(1u));
        unsigned int guard = 0;
        while (ld_acq(cnt) < target) {
            __nanosleep(32);
            if (++guard > 30000000u) break;
        }
    }
    __syncthreads();
}

__global__ void reset_sync(unsigned int* p) { p[0] = 0; p[1] = 0; p[2] = 0; p[3] = 0; }

// ---------------- persistent bidirectional LSTM recurrence (tensor cores) ----
// Per step per CTA: C[32b x 32col] = h[32 x 512] x W[512 x 32col] via
// mma.sync.m16n8k8.tf32, 3-term split (AhiBhi + AhiBlo + AloBhi; error ~2^-22).
// 8 warps, warp tile 16x8 (mi=warp>>2, ni=warp&3), full K=512 (64 kt).
// smem: Whi/Wlo [32col][516] (pre-split once; static), hfp [32b][516] fp32
// (staged per step from seq), cs [32][33] (C staging for epilogue).
// Pitch 516 = 4 (mod 32) -> all fragment LDS patterns (8 rows x 4 cols) hit 32
// distinct banks: conflict-free. A-frags split hi/lo in regs via cvt.rna.tf32.
// Epilogue: thread t = (b = t>>3, jl = t&7) owns gates/c-state/h-store/avg.
// Barrier/prefetch machinery identical to R12 (4 passing rounds).
#define WP 516
#define SM_WHI 0
#define SM_WLO (32 * WP)
#define SM_HFP (2 * 32 * WP)
#define SM_CS  (3 * 32 * WP)
#define LSTM_SMEM ((3 * 32 * WP + 32 * 33) * 4)   // 202368 B

__device__ __forceinline__ float sigmoidf(float x) { return 1.f / (1.f + expf(-x)); }

__global__ __launch_bounds__(256) void lstm_persist(
    const float* __restrict__ xg0, const float* __restrict__ xg1,
    const float* __restrict__ Whh0, const float* __restrict__ Whh1,
    float* __restrict__ seq,   // [B*T, 1024]: fwd cols 0..511, bwd 512..1023
    float* __restrict__ avg,   // [B, 1024] or nullptr
    unsigned int* __restrict__ sync_base)
{
    extern __shared__ float smem[];
    float* whi = smem + SM_WHI;
    float* wlo = smem + SM_WLO;
    float* hfp = smem + SM_HFP;
    float* cs  = smem + SM_CS;

    const int tid  = threadIdx.x;
    const int dir  = blockIdx.y;
    const int lane = tid & 31;
    const int warp = tid >> 5;
    const int jbase = blockIdx.x << 3;
    unsigned int* sync_cnt = sync_base + dir;

    // One-time: split W into smem hi/lo. col = jl*4 + gate -> Whh row gate*512+jbase+jl.
    const float* whh = dir ? Whh1 : Whh0;
    for (int idx = tid; idx < 32 * 128; idx += 256) {   // float4 granules
        int col = idx >> 7;
        int q   = idx & 127;
        int jl = col >> 2, gate = col & 3;
        float4 v = ((const float4*)(whh + (size_t)(gate * 512 + jbase + jl) * 512))[q];
        float4 hv, lv;
        hv.x = tf32_round(v.x); lv.x = tf32_round(v.x - hv.x);
        hv.y = tf32_round(v.y); lv.y = tf32_round(v.y - hv.y);
        hv.z = tf32_round(v.z); lv.z = tf32_round(v.z - hv.z);
        hv.w = tf32_round(v.w); lv.w = tf32_round(v.w - hv.w);
        *(float4*)&whi[col * WP + q * 4] = hv;
        *(float4*)&wlo[col * WP + q * 4] = lv;
    }
    // zero h for step 0
    for (int i = tid; i < 32 * WP; i += 256) hfp[i] = 0.f;

    const float* xg = dir ? xg1 : xg0;
    const unsigned int nb = gridDim.x;          // 64 CTAs per direction
    unsigned int target = 0;

    // epilogue identity: b = tid>>3, jl = tid&7
    const int eb = tid >> 3;
    const int ej = jbase + (tid & 7);
    float cstate = 0.f;
    float hsum = 0.f;

    // xg prefetch for step 0
    float pxi, pxf, pxg, pxo;
    {
        int t0 = dir ? (Tlen - 1) : 0;
        int bs = (eb * Tlen + t0) * 2048;
        pxi = xg[bs + ej];        pxf = xg[bs + 512 + ej];
        pxg = xg[bs + 1024 + ej]; pxo = xg[bs + 1536 + ej];
    }

    // mma fragment base pointers (constant across steps)
    const int mi = warp >> 2, ni = warp & 3;
    const float* A0 = hfp + (mi * 16 + (lane >> 2)) * WP + (lane & 3);
    const float* A1 = A0 + 8 * WP;
    const float* Bh = whi + (ni * 8 + (lane >> 2)) * WP + (lane & 3);
    const float* Bl = wlo + (ni * 8 + (lane >> 2)) * WP + (lane & 3);

    for (int s = 0; s < Tlen; ++s) {
        const int tcur = dir ? (Tlen - 1 - s) : s;

        if (s > 0) {
            const int tprev = dir ? (tcur + 1) : (tcur - 1);
            const int lb  = tid >> 3;            // 0..31 batch
            const int klo = (tid & 7) << 2;      // 0,4,...,28
            const float* hp = seq + (size_t)(lb * Tlen + tprev) * 1024 + dir * 512;
#pragma unroll
            for (int it = 0; it < 16; ++it) {
                int k = klo + (it << 5);         // < 512
                float4 v = *(const float4*)(hp + k);
                *(float4*)&hfp[lb * WP + k] = v;
            }
        }
        __syncthreads();

        // tensor-core matvec: warp tile 16x8 over K=512
        float cc[4] = {0.f, 0.f, 0.f, 0.f};
#pragma unroll 4
        for (int kt = 0; kt < 64; ++kt) {
            const int o = kt * 8;
            float f0 = A0[o], f1 = A1[o], f2 = A0[o + 4], f3 = A1[o + 4];
            unsigned ah[4], al[4], bh[2], bl[2];
            ah[0] = tf32_bits(f0); ah[1] = tf32_bits(f1);
            ah[2] = tf32_bits(f2); ah[3] = tf32_bits(f3);
            al[0] = tf32_bits(f0 - __uint_as_float(ah[0]));
            al[1] = tf32_bits(f1 - __uint_as_float(ah[1]));
            al[2] = tf32_bits(f2 - __uint_as_float(ah[2]));
            al[3] = tf32_bits(f3 - __uint_as_float(ah[3]));
            bh[0] = __float_as_uint(Bh[o]); bh[1] = __float_as_uint(Bh[o + 4]);
            bl[0] = __float_as_uint(Bl[o]); bl[1] = __float_as_uint(Bl[o + 4]);
            mma_tf32(cc, ah, bh);
            mma_tf32(cc, ah, bl);
            mma_tf32(cc, al, bh);
        }
        // store C fragments to cs [32][33]
        {
            int r0 = mi * 16 + (lane >> 2);
            int nc = ni * 8 + 2 * (lane & 3);
            cs[r0 * 33 + nc]           = cc[0];
            cs[r0 * 33 + nc + 1]       = cc[1];
            cs[(r0 + 8) * 33 + nc]     = cc[2];
            cs[(r0 + 8) * 33 + nc + 1] = cc[3];
        }
        __syncthreads();

        // epilogue: thread (eb, ej)
        {
            int base = eb * 33 + (tid & 7) * 4;
            float gi = cs[base + 0] + pxi;
            float gf = cs[base + 1] + pxf;
            float gg = cs[base + 2] + pxg;
            float go = cs[base + 3] + pxo;
            cstate = sigmoidf(gf) * cstate + sigmoidf(gi) * tanhf(gg);
            float h = sigmoidf(go) * tanhf(cstate);
            seq[(size_t)(eb * Tlen + tcur) * 1024 + dir * 512 + ej] = h;
            hsum += h;
        }

        if (s + 1 < Tlen) {
            // prefetch next step's xg before the barrier (hidden by the spin)
            int tn = dir ? (tcur - 1) : (tcur + 1);
            int bs = (eb * Tlen + tn) * 2048;
            pxi = xg[bs + ej];        pxf = xg[bs + 512 + ej];
            pxg = xg[bs + 1024 + ej]; pxo = xg[bs + 1536 + ej];

            target += nb;
            grid_sync(sync_cnt, target);   // also guards hfp/cs overwrite
        }
    }

    if (avg) avg[eb * 1024 + dir * 512 + ej] = hsum * (1.f / Tlen);
}

// ---------------- launch ------------------------------------------------------
extern "C" void kernel_launch(void* const* d_in, const int* in_sizes, int n_in,
                              void* d_out, int out_size)
{
    const float* x     = (const float*)d_in[0];
    const float* Wih0f = (const float*)d_in[1];
    const float* Whh0f = (const float*)d_in[2];
    const float* b0f   = (const float*)d_in[3];
    const float* Wih0b = (const float*)d_in[4];
    const float* Whh0b = (const float*)d_in[5];
    const float* b0b   = (const float*)d_in[6];
    const float* Wih1f = (const float*)d_in[7];
    const float* Whh1f = (const float*)d_in[8];
    const float* b1f   = (const float*)d_in[9];
    const float* Wih1b = (const float*)d_in[10];
    const float* Whh1b = (const float*)d_in[11];
    const float* b1b   = (const float*)d_in[12];

    float* avg    = (float*)d_out;
    float* outseq = avg + Bsz * 2 * Hd;   // avg_out first, then out [B,T,1024]

    float *xg0, *xg1, *x1;
    unsigned int* syncp;
    cudaGetSymbolAddress((void**)&xg0, g_xg0);
    cudaGetSymbolAddress((void**)&xg1, g_xg1);
    cudaGetSymbolAddress((void**)&x1,  g_x1);
    cudaGetSymbolAddress((void**)&syncp, g_sync);

    cudaFuncSetAttribute(lstm_persist, cudaFuncAttributeMaxDynamicSharedMemorySize, LSTM_SMEM);
    cudaFuncSetAttribute(tf32_gemm_bias, cudaFuncAttributeMaxDynamicSharedMemorySize, GEMM_SMEM);

    dim3 gemm_grid(2048 / 128, 16384 / 128);     // (16, 128)
    dim3 step_grid(64, 2);

    reset_sync<<<1, 1>>>(syncp);

    // Layer 0 input gates (tensor cores, tf32 2-term split)
    tf32_gemm_bias<<<gemm_grid, 256, GEMM_SMEM>>>(x, Wih0f, b0f, xg0, 16384, 2048, 512);
    tf32_gemm_bias<<<gemm_grid, 256, GEMM_SMEM>>>(x, Wih0b, b0b, xg1, 16384, 2048, 512);
    // Layer 0 recurrence (persistent tensor-core, per-dir grid-sync: counters 0,1)
    lstm_persist<<<step_grid, 256, LSTM_SMEM>>>(xg0, xg1, Whh0f, Whh0b, x1, nullptr, syncp);
    // Layer 1 input gates (K = 1024)
    tf32_gemm_bias<<<gemm_grid, 256, GEMM_SMEM>>>(x1, Wih1f, b1f, xg0, 16384, 2048, 1024);
    tf32_gemm_bias<<<gemm_grid, 256, GEMM_SMEM>>>(x1, Wih1b, b1b, xg1, 16384, 2048, 1024);
    // Layer 1 recurrence -> out region of d_out, mean fused (counters 2,3)
    lstm_persist<<<step_grid, 256, LSTM_SMEM>>>(xg0, xg1, Whh1f, Whh1b, outseq, avg, syncp + 2);
}

// round 14
// speedup vs baseline: 1.7127x; 1.1657x over previous
#include <cuda_runtime.h>
#include <cuda_bf16.h>
#include <math.h>

#define Bsz 32
#define Tlen 512
#define Hd 512

// ---------------- scratch (static device globals per harness rules) ----------
__device__ float g_xg0[(size_t)Bsz * Tlen * 4 * Hd];   // 134 MB  (dir 0 gates)
__device__ float g_xg1[(size_t)Bsz * Tlen * 4 * Hd];   // 134 MB  (dir 1 gates)
__device__ float g_x1[(size_t)Bsz * Tlen * 2 * Hd];    // 64 MB   (layer-0 output)
__device__ unsigned int g_sync[4];                     // per-layer, per-dir barriers

// ---------------- tf32 helpers (GEMM) -----------------------------------------
__device__ __forceinline__ float tf32_round(float v) {
    unsigned r;
    asm("cvt.rna.tf32.f32 %0, %1;" : "=r"(r) : "f"(v));
    return __uint_as_float(r);
}
__device__ __forceinline__ void mma_tf32(float* c, const unsigned* a, const unsigned* b) {
    asm volatile(
        "mma.sync.aligned.m16n8k8.row.col.f32.tf32.tf32.f32 "
        "{%0,%1,%2,%3}, {%4,%5,%6,%7}, {%8,%9}, {%0,%1,%2,%3};"
        : "+f"(c[0]), "+f"(c[1]), "+f"(c[2]), "+f"(c[3])
        : "r"(a[0]), "r"(a[1]), "r"(a[2]), "r"(a[3]), "r"(b[0]), "r"(b[1]));
}

// ---------------- bf16 helpers (recurrence) -----------------------------------
__device__ __forceinline__ void mma_bf16(float* c, const unsigned* a, const unsigned* b) {
    asm volatile(
        "mma.sync.aligned.m16n8k16.row.col.f32.bf16.bf16.f32 "
        "{%0,%1,%2,%3}, {%4,%5,%6,%7}, {%8,%9}, {%0,%1,%2,%3};"
        : "+f"(c[0]), "+f"(c[1]), "+f"(c[2]), "+f"(c[3])
        : "r"(a[0]), "r"(a[1]), "r"(a[2]), "r"(a[3]), "r"(b[0]), "r"(b[1]));
}
// split f into bf16 hi + bf16 lo (value = hi + lo to ~16-17 mantissa bits)
__device__ __forceinline__ void split_bf16(float f, unsigned short& h, unsigned short& l) {
    __nv_bfloat16 bh = __float2bfloat16_rn(f);
    float fh = __bfloat162float(bh);
    __nv_bfloat16 bl = __float2bfloat16_rn(f - fh);
    h = __bfloat16_as_ushort(bh);
    l = __bfloat16_as_ushort(bl);
}

// ---------------- TF32 2-term split GEMM: C = A*W^T + bias --------------------
#define HSTR 12
#define TILE_F (2 * 128 * HSTR)
#define BUF_F  (3 * TILE_F)
#define GEMM_SMEM (2 * BUF_F * 4)

__global__ __launch_bounds__(256) void tf32_gemm_bias(
    const float* __restrict__ A, const float* __restrict__ W,
    const float* __restrict__ bias, float* __restrict__ C,
    int M, int N, int K)
{
    extern __shared__ float sm[];
    const int tid  = threadIdx.x;
    const int lane = tid & 31;
    const int warp = tid >> 5;
    const int gid  = lane >> 2;
    const int tig  = lane & 3;
    const int bx = blockIdx.x, by = blockIdx.y;
    const int mo = (warp >> 2) * 64;
    const int no = (warp & 3) * 32;

    const int lrow = tid >> 2;
    const int lkq  = (tid & 3) << 2;
    const int lhalf = lkq >> 3;
    const int lkoff = lkq & 7;

    const float* Ag0 = A + (size_t)(by * 128 + lrow) * K + lkq;
    const float* Ag1 = A + (size_t)(by * 128 + lrow + 64) * K + lkq;
    const float* Wg0 = W + (size_t)(bx * 128 + lrow) * K + lkq;
    const float* Wg1 = W + (size_t)(bx * 128 + lrow + 64) * K + lkq;

    float c[4][4][4];
#pragma unroll
    for (int mt = 0; mt < 4; mt++)
#pragma unroll
        for (int nt = 0; nt < 4; nt++)
#pragma unroll
            for (int i = 0; i < 4; i++) c[mt][nt][i] = 0.f;

    const int nk = K >> 4;
    float4 ra0, ra1, rb0, rb1;

    ra0 = *(const float4*)Ag0; ra1 = *(const float4*)Ag1;
    rb0 = *(const float4*)Wg0; rb1 = *(const float4*)Wg1;

    auto sts_a = [&](int p, float4 v, int row) {
        float* dst = sm + p * BUF_F + lhalf * 1536 + row * HSTR + lkoff;
        float4 hv;
        hv.x = tf32_round(v.x); hv.y = tf32_round(v.y);
        hv.z = tf32_round(v.z); hv.w = tf32_round(v.w);
        *(float4*)dst = hv;
    };
    auto sts_b = [&](int p, float4 v, int row) {
        float* dst_h = sm + p * BUF_F + TILE_F + lhalf * 1536 + row * HSTR + lkoff;
        float4 hv, lv;
        hv.x = tf32_round(v.x); lv.x = tf32_round(v.x - hv.x);
        hv.y = tf32_round(v.y); lv.y = tf32_round(v.y - hv.y);
        hv.z = tf32_round(v.z); lv.z = tf32_round(v.z - hv.z);
        hv.w = tf32_round(v.w); lv.w = tf32_round(v.w - hv.w);
        *(float4*)dst_h = hv;
        *(float4*)(dst_h + TILE_F) = lv;
    };

    sts_a(0, ra0, lrow);
    sts_a(0, ra1, lrow + 64);
    sts_b(0, rb0, lrow);
    sts_b(0, rb1, lrow + 64);
    __syncthreads();

    int p = 0;
    for (int kt = 0; kt < nk; ++kt) {
        if (kt + 1 < nk) {
            const int k0 = (kt + 1) << 4;
            ra0 = *(const float4*)(Ag0 + k0); ra1 = *(const float4*)(Ag1 + k0);
            rb0 = *(const float4*)(Wg0 + k0); rb1 = *(const float4*)(Wg1 + k0);
        }

#pragma unroll
        for (int h = 0; h < 2; ++h) {
            const float* sA_h = sm + p * BUF_F + h * 1536;
            const float* sB_h = sA_h + TILE_F;
            const float* sB_l = sA_h + 2 * TILE_F;

            unsigned ah[4][4], bh[4][2], bl[4][2];
#pragma unroll
            for (int mt = 0; mt < 4; mt++) {
                int r0 = (mo + mt * 16 + gid) * HSTR + tig;
                ah[mt][0] = __float_as_uint(sA_h[r0]);
                ah[mt][1] = __float_as_uint(sA_h[r0 + 8 * HSTR]);
                ah[mt][2] = __float_as_uint(sA_h[r0 + 4]);
                ah[mt][3] = __float_as_uint(sA_h[r0 + 8 * HSTR + 4]);
            }
#pragma unroll
            for (int nt = 0; nt < 4; nt++) {
                int n0 = (no + nt * 8 + gid) * HSTR + tig;
                bh[nt][0] = __float_as_uint(sB_h[n0]);
                bh[nt][1] = __float_as_uint(sB_h[n0 + 4]);
                bl[nt][0] = __float_as_uint(sB_l[n0]);
                bl[nt][1] = __float_as_uint(sB_l[n0 + 4]);
            }
#pragma unroll
            for (int mt = 0; mt < 4; mt++)
#pragma unroll
                for (int nt = 0; nt < 4; nt++) {
                    mma_tf32(c[mt][nt], ah[mt], bh[nt]);
                    mma_tf32(c[mt][nt], ah[mt], bl[nt]);
                }
        }

        if (kt + 1 < nk) {
            sts_a(1 - p, ra0, lrow);
            sts_a(1 - p, ra1, lrow + 64);
            sts_b(1 - p, rb0, lrow);
            sts_b(1 - p, rb1, lrow + 64);
        }
        __syncthreads();
        p ^= 1;
    }

#pragma unroll
    for (int nt = 0; nt < 4; nt++) {
        int col = bx * 128 + no + nt * 8 + tig * 2;
        float bv0 = bias[col], bv1 = bias[col + 1];
#pragma unroll
        for (int mt = 0; mt < 4; mt++) {
            int row0 = by * 128 + mo + mt * 16 + gid;
            float2 v0 = make_float2(c[mt][nt][0] + bv0, c[mt][nt][1] + bv1);
            float2 v1 = make_float2(c[mt][nt][2] + bv0, c[mt][nt][3] + bv1);
            *(float2*)(C + (size_t)row0 * N + col) = v0;
            *(float2*)(C + (size_t)(row0 + 8) * N + col) = v1;
        }
    }
}

// ---------------- grid barrier helpers ---------------------------------------
__device__ __forceinline__ unsigned int ld_acq(const unsigned int* p) {
    unsigned int v;
    asm volatile("ld.acquire.gpu.global.u32 %0, [%1];" : "=r"(v) : "l"(p));
    return v;
}
__device__ __forceinline__ void grid_sync(unsigned int* cnt, unsigned int target) {
    __syncthreads();
    if (threadIdx.x == 0) {
        asm volatile("red.release.gpu.global.add.u32 [%0], %1;" :: "l"(cnt), "r"(1u));
        unsigned int guard = 0;
        while (ld_acq(cnt) < target) {
            __nanosleep(32);
            if (++guard > 30000000u) break;
        }
    }
    __syncthreads();
}

__global__ void reset_sync(unsigned int* p) { p[0] = 0; p[1] = 0; p[2] = 0; p[3] = 0; }

// ---------------- persistent bidirectional LSTM recurrence (bf16 mma) ---------
// Per step per CTA: C[32b x 32col] = h[32 x 512] x W[512 x 32col] via
// mma.sync.m16n8k16.bf16, 3-term split (AhiBhi + AhiBlo + AloBhi; dropped
// AloBlo ~2^-16). W split bf16 hi/lo ONCE (static); h split ONCE PER STEP at
// staging (kills R13's per-kt cvt.rna chains that pinned alu at 25%).
// Layout (word pitch 260 per row = 520 bf16): fragment word index = 4*r + c
// (mod 32) over r=0..7, c=0..3 (+4 variants) -> 32 distinct banks, no
// conflicts, for both A [row][k] and B [col][k].
// 8 warps, warp tile 16x8, 32 kt of k16. Inner kt: 12 LDS.32 + 3 mma, 0 cvt.
// Epilogue thread t = (b=t>>3, jl=t&7): gates/c-state/h-store/avg (R13 exact).
// smem: whi/wlo/hhi/hlo 4 x 8320 words + cs 32x33 f32 = 137,344 B. 1 CTA/SM.
#define RWP 260                     // word pitch per row (520 bf16)
#define LSTM_SMEM (4 * 32 * RWP * 4 + 32 * 33 * 4)   // 137344 B

__device__ __forceinline__ float sigmoidf(float x) { return 1.f / (1.f + expf(-x)); }

__global__ __launch_bounds__(256) void lstm_persist(
    const float* __restrict__ xg0, const float* __restrict__ xg1,
    const float* __restrict__ Whh0, const float* __restrict__ Whh1,
    float* __restrict__ seq,   // [B*T, 1024]: fwd cols 0..511, bwd 512..1023
    float* __restrict__ avg,   // [B, 1024] or nullptr
    unsigned int* __restrict__ sync_base)
{
    extern __shared__ unsigned smw[];
    unsigned* whiu = smw;                    // [32 col][260 w]
    unsigned* wlou = smw + 32 * RWP;
    unsigned* hhiu = smw + 2 * 32 * RWP;     // [32 b][260 w]
    unsigned* hlou = smw + 3 * 32 * RWP;
    float*    cs   = (float*)(smw + 4 * 32 * RWP);   // [32][33]

    const int tid  = threadIdx.x;
    const int dir  = blockIdx.y;
    const int lane = tid & 31;
    const int warp = tid >> 5;
    const int jbase = blockIdx.x << 3;
    unsigned int* sync_cnt = sync_base + dir;

    // One-time: split W into bf16 hi/lo. col = jl*4 + gate -> row gate*512+jbase+jl.
    const float* whh = dir ? Whh1 : Whh0;
    for (int idx = tid; idx < 32 * 128; idx += 256) {   // float4 granules (k = 4q)
        int col = idx >> 7;
        int q   = idx & 127;
        int jl = col >> 2, gate = col & 3;
        float4 v = ((const float4*)(whh + (size_t)(gate * 512 + jbase + jl) * 512))[q];
        unsigned short h0, l0, h1, l1, h2, l2, h3, l3;
        split_bf16(v.x, h0, l0); split_bf16(v.y, h1, l1);
        split_bf16(v.z, h2, l2); split_bf16(v.w, h3, l3);
        int w = col * RWP + 2 * q;          // word index (k/2)
        whiu[w]     = (unsigned)h0 | ((unsigned)h1 << 16);
        whiu[w + 1] = (unsigned)h2 | ((unsigned)h3 << 16);
        wlou[w]     = (unsigned)l0 | ((unsigned)l1 << 16);
        wlou[w + 1] = (unsigned)l2 | ((unsigned)l3 << 16);
    }
    // zero h hi/lo for step 0 (2 x 8320 words)
    for (int i = tid; i < 2 * 32 * RWP; i += 256) hhiu[i] = 0u;   // covers hhiu+hlou

    const float* xg = dir ? xg1 : xg0;
    const unsigned int nb = gridDim.x;          // 64 CTAs per direction
    unsigned int target = 0;

    // epilogue identity: b = tid>>3, jl = tid&7
    const int eb = tid >> 3;
    const int ej = jbase + (tid & 7);
    float cstate = 0.f;
    float hsum = 0.f;

    // xg prefetch for step 0
    float pxi, pxf, pxg, pxo;
    {
        int t0 = dir ? (Tlen - 1) : 0;
        int bs = (eb * Tlen + t0) * 2048;
        pxi = xg[bs + ej];        pxf = xg[bs + 512 + ej];
        pxg = xg[bs + 1024 + ej]; pxo = xg[bs + 1536 + ej];
    }

    // mma fragment base pointers (constant across steps)
    const int mi = warp >> 2, ni = warp & 3;
    const int qr = lane >> 2, qc = lane & 3;
    const unsigned* Ah = hhiu + (mi * 16 + qr) * RWP + qc;   // a1 at +8*RWP, a2 at +4
    const unsigned* Al = hlou + (mi * 16 + qr) * RWP + qc;
    const unsigned* Bh = whiu + (ni * 8 + qr) * RWP + qc;    // b1 at +4
    const unsigned* Bl = wlou + (ni * 8 + qr) * RWP + qc;

    for (int s = 0; s < Tlen; ++s) {
        const int tcur = dir ? (Tlen - 1 - s) : s;

        if (s > 0) {
            const int tprev = dir ? (tcur + 1) : (tcur - 1);
            const int lb  = tid >> 3;            // 0..31 batch
            const int klo = (tid & 7) << 2;      // 0,4,...,28
            const float* hp = seq + (size_t)(lb * Tlen + tprev) * 1024 + dir * 512;
#pragma unroll
            for (int it = 0; it < 16; ++it) {
                int k = klo + (it << 5);         // < 512, multiple of 4
                float4 v = *(const float4*)(hp + k);
                unsigned short h0, l0, h1, l1, h2, l2, h3, l3;
                split_bf16(v.x, h0, l0); split_bf16(v.y, h1, l1);
                split_bf16(v.z, h2, l2); split_bf16(v.w, h3, l3);
                int w = lb * RWP + (k >> 1);
                hhiu[w]     = (unsigned)h0 | ((unsigned)h1 << 16);
                hhiu[w + 1] = (unsigned)h2 | ((unsigned)h3 << 16);
                hlou[w]     = (unsigned)l0 | ((unsigned)l1 << 16);
                hlou[w + 1] = (unsigned)l2 | ((unsigned)l3 << 16);
            }
        }
        __syncthreads();

        // tensor-core matvec: warp tile 16x8, 32 kt of k16, 3-term bf16
        float cc[4] = {0.f, 0.f, 0.f, 0.f};
#pragma unroll 4
        for (int kt = 0; kt < 32; ++kt) {
            const int o = kt * 8;               // 8 words = 16 bf16 per kt
            unsigned ah[4], al[4], bh[2], bl[2];
            ah[0] = Ah[o];            ah[1] = Ah[o + 8 * RWP];
            ah[2] = Ah[o + 4];        ah[3] = Ah[o + 8 * RWP + 4];
            al[0] = Al[o];            al[1] = Al[o + 8 * RWP];
            al[2] = Al[o + 4];        al[3] = Al[o + 8 * RWP + 4];
            bh[0] = Bh[o];            bh[1] = Bh[o + 4];
            bl[0] = Bl[o];            bl[1] = Bl[o + 4];
            mma_bf16(cc, ah, bh);
            mma_bf16(cc, ah, bl);
            mma_bf16(cc, al, bh);
        }
        // store C fragments to cs [32][33]
        {
            int r0 = mi * 16 + qr;
            int nc = ni * 8 + 2 * qc;
            cs[r0 * 33 + nc]           = cc[0];
            cs[r0 * 33 + nc + 1]       = cc[1];
            cs[(r0 + 8) * 33 + nc]     = cc[2];
            cs[(r0 + 8) * 33 + nc + 1] = cc[3];
        }
        __syncthreads();

        // epilogue: thread (eb, ej)
        {
            int base = eb * 33 + (tid & 7) * 4;
            float gi = cs[base + 0] + pxi;
            float gf = cs[base + 1] + pxf;
            float gg = cs[base + 2] + pxg;
            float go = cs[base + 3] + pxo;
            cstate = sigmoidf(gf) * cstate + sigmoidf(gi) * tanhf(gg);
            float h = sigmoidf(go) * tanhf(cstate);
            seq[(size_t)(eb * Tlen + tcur) * 1024 + dir * 512 + ej] = h;
            hsum += h;
        }

        if (s + 1 < Tlen) {
            // prefetch next step's xg before the barrier (hidden by the spin)
            int tn = dir ? (tcur - 1) : (tcur + 1);
            int bs = (eb * Tlen + tn) * 2048;
            pxi = xg[bs + ej];        pxf = xg[bs + 512 + ej];
            pxg = xg[bs + 1024 + ej]; pxo = xg[bs + 1536 + ej];

            target += nb;
            grid_sync(sync_cnt, target);   // also guards hhiu/hlou/cs overwrite
        }
    }

    if (avg) avg[eb * 1024 + dir * 512 + ej] = hsum * (1.f / Tlen);
}

// ---------------- launch ------------------------------------------------------
extern "C" void kernel_launch(void* const* d_in, const int* in_sizes, int n_in,
                              void* d_out, int out_size)
{
    const float* x     = (const float*)d_in[0];
    const float* Wih0f = (const float*)d_in[1];
    const float* Whh0f = (const float*)d_in[2];
    const float* b0f   = (const float*)d_in[3];
    const float* Wih0b = (const float*)d_in[4];
    const float* Whh0b = (const float*)d_in[5];
    const float* b0b   = (const float*)d_in[6];
    const float* Wih1f = (const float*)d_in[7];
    const float* Whh1f = (const float*)d_in[8];
    const float* b1f   = (const float*)d_in[9];
    const float* Wih1b = (const float*)d_in[10];
    const float* Whh1b = (const float*)d_in[11];
    const float* b1b   = (const float*)d_in[12];

    float* avg    = (float*)d_out;
    float* outseq = avg + Bsz * 2 * Hd;   // avg_out first, then out [B,T,1024]

    float *xg0, *xg1, *x1;
    unsigned int* syncp;
    cudaGetSymbolAddress((void**)&xg0, g_xg0);
    cudaGetSymbolAddress((void**)&xg1, g_xg1);
    cudaGetSymbolAddress((void**)&x1,  g_x1);
    cudaGetSymbolAddress((void**)&syncp, g_sync);

    cudaFuncSetAttribute(lstm_persist, cudaFuncAttributeMaxDynamicSharedMemorySize, LSTM_SMEM);
    cudaFuncSetAttribute(tf32_gemm_bias, cudaFuncAttributeMaxDynamicSharedMemorySize, GEMM_SMEM);

    dim3 gemm_grid(2048 / 128, 16384 / 128);     // (16, 128)
    dim3 step_grid(64, 2);

    reset_sync<<<1, 1>>>(syncp);

    // Layer 0 input gates (tensor cores, tf32 2-term split)
    tf32_gemm_bias<<<gemm_grid, 256, GEMM_SMEM>>>(x, Wih0f, b0f, xg0, 16384, 2048, 512);
    tf32_gemm_bias<<<gemm_grid, 256, GEMM_SMEM>>>(x, Wih0b, b0b, xg1, 16384, 2048, 512);
    // Layer 0 recurrence (persistent bf16 tensor-core, counters 0,1)
    lstm_persist<<<step_grid, 256, LSTM_SMEM>>>(xg0, xg1, Whh0f, Whh0b, x1, nullptr, syncp);
    // Layer 1 input gates (K = 1024)
    tf32_gemm_bias<<<gemm_grid, 256, GEMM_SMEM>>>(x1, Wih1f, b1f, xg0, 16384, 2048, 1024);
    tf32_gemm_bias<<<gemm_grid, 256, GEMM_SMEM>>>(x1, Wih1b, b1b, xg1, 16384, 2048, 1024);
    // Layer 1 recurrence -> out region of d_out, mean fused (counters 2,3)
    lstm_persist<<<step_grid, 256, LSTM_SMEM>>>(xg0, xg1, Whh1f, Whh1b, outseq, avg, syncp + 2);
}

// round 15
// speedup vs baseline: 2.0576x; 1.2013x over previous
#include <cuda_runtime.h>
#include <cuda_bf16.h>
#include <math.h>

#define Bsz 32
#define Tlen 512
#define Hd 512

// ---------------- scratch (static device globals per harness rules) ----------
__device__ float g_xg0[(size_t)Bsz * Tlen * 4 * Hd];   // 134 MB  (dir 0 gates)
__device__ float g_xg1[(size_t)Bsz * Tlen * 4 * Hd];   // 134 MB  (dir 1 gates)
__device__ float g_x1[(size_t)Bsz * Tlen * 2 * Hd];    // 64 MB   (layer-0 output)
__device__ unsigned short g_hhi[2][Tlen][Bsz][512];    // 32 MB  (h bf16 hi plane)
__device__ unsigned short g_hlo[2][Tlen][Bsz][512];    // 32 MB  (h bf16 lo plane)
__device__ unsigned int g_sync[4];                     // per-layer, per-dir barriers

// ---------------- tf32 helpers (GEMM) -----------------------------------------
__device__ __forceinline__ float tf32_round(float v) {
    unsigned r;
    asm("cvt.rna.tf32.f32 %0, %1;" : "=r"(r) : "f"(v));
    return __uint_as_float(r);
}
__device__ __forceinline__ void mma_tf32(float* c, const unsigned* a, const unsigned* b) {
    asm volatile(
        "mma.sync.aligned.m16n8k8.row.col.f32.tf32.tf32.f32 "
        "{%0,%1,%2,%3}, {%4,%5,%6,%7}, {%8,%9}, {%0,%1,%2,%3};"
        : "+f"(c[0]), "+f"(c[1]), "+f"(c[2]), "+f"(c[3])
        : "r"(a[0]), "r"(a[1]), "r"(a[2]), "r"(a[3]), "r"(b[0]), "r"(b[1]));
}

// ---------------- bf16 helpers (recurrence) -----------------------------------
__device__ __forceinline__ void mma_bf16(float* c, const unsigned* a, const unsigned* b) {
    asm volatile(
        "mma.sync.aligned.m16n8k16.row.col.f32.bf16.bf16.f32 "
        "{%0,%1,%2,%3}, {%4,%5,%6,%7}, {%8,%9}, {%0,%1,%2,%3};"
        : "+f"(c[0]), "+f"(c[1]), "+f"(c[2]), "+f"(c[3])
        : "r"(a[0]), "r"(a[1]), "r"(a[2]), "r"(a[3]), "r"(b[0]), "r"(b[1]));
}
__device__ __forceinline__ void split_bf16(float f, unsigned short& h, unsigned short& l) {
    __nv_bfloat16 bh = __float2bfloat16_rn(f);
    float fh = __bfloat162float(bh);
    __nv_bfloat16 bl = __float2bfloat16_rn(f - fh);
    h = __bfloat16_as_ushort(bh);
    l = __bfloat16_as_ushort(bl);
}

// ---------------- TF32 2-term split GEMM: C = A*W^T + bias --------------------
#define HSTR 12
#define TILE_F (2 * 128 * HSTR)
#define BUF_F  (3 * TILE_F)
#define GEMM_SMEM (2 * BUF_F * 4)

__global__ __launch_bounds__(256) void tf32_gemm_bias(
    const float* __restrict__ A, const float* __restrict__ W,
    const float* __restrict__ bias, float* __restrict__ C,
    int M, int N, int K)
{
    extern __shared__ float sm[];
    const int tid  = threadIdx.x;
    const int lane = tid & 31;
    const int warp = tid >> 5;
    const int gid  = lane >> 2;
    const int tig  = lane & 3;
    const int bx = blockIdx.x, by = blockIdx.y;
    const int mo = (warp >> 2) * 64;
    const int no = (warp & 3) * 32;

    const int lrow = tid >> 2;
    const int lkq  = (tid & 3) << 2;
    const int lhalf = lkq >> 3;
    const int lkoff = lkq & 7;

    const float* Ag0 = A + (size_t)(by * 128 + lrow) * K + lkq;
    const float* Ag1 = A + (size_t)(by * 128 + lrow + 64) * K + lkq;
    const float* Wg0 = W + (size_t)(bx * 128 + lrow) * K + lkq;
    const float* Wg1 = W + (size_t)(bx * 128 + lrow + 64) * K + lkq;

    float c[4][4][4];
#pragma unroll
    for (int mt = 0; mt < 4; mt++)
#pragma unroll
        for (int nt = 0; nt < 4; nt++)
#pragma unroll
            for (int i = 0; i < 4; i++) c[mt][nt][i] = 0.f;

    const int nk = K >> 4;
    float4 ra0, ra1, rb0, rb1;

    ra0 = *(const float4*)Ag0; ra1 = *(const float4*)Ag1;
    rb0 = *(const float4*)Wg0; rb1 = *(const float4*)Wg1;

    auto sts_a = [&](int p, float4 v, int row) {
        float* dst = sm + p * BUF_F + lhalf * 1536 + row * HSTR + lkoff;
        float4 hv;
        hv.x = tf32_round(v.x); hv.y = tf32_round(v.y);
        hv.z = tf32_round(v.z); hv.w = tf32_round(v.w);
        *(float4*)dst = hv;
    };
    auto sts_b = [&](int p, float4 v, int row) {
        float* dst_h = sm + p * BUF_F + TILE_F + lhalf * 1536 + row * HSTR + lkoff;
        float4 hv, lv;
        hv.x = tf32_round(v.x); lv.x = tf32_round(v.x - hv.x);
        hv.y = tf32_round(v.y); lv.y = tf32_round(v.y - hv.y);
        hv.z = tf32_round(v.z); lv.z = tf32_round(v.z - hv.z);
        hv.w = tf32_round(v.w); lv.w = tf32_round(v.w - hv.w);
        *(float4*)dst_h = hv;
        *(float4*)(dst_h + TILE_F) = lv;
    };

    sts_a(0, ra0, lrow);
    sts_a(0, ra1, lrow + 64);
    sts_b(0, rb0, lrow);
    sts_b(0, rb1, lrow + 64);
    __syncthreads();

    int p = 0;
    for (int kt = 0; kt < nk; ++kt) {
        if (kt + 1 < nk) {
            const int k0 = (kt + 1) << 4;
            ra0 = *(const float4*)(Ag0 + k0); ra1 = *(const float4*)(Ag1 + k0);
            rb0 = *(const float4*)(Wg0 + k0); rb1 = *(const float4*)(Wg1 + k0);
        }

#pragma unroll
        for (int h = 0; h < 2; ++h) {
            const float* sA_h = sm + p * BUF_F + h * 1536;
            const float* sB_h = sA_h + TILE_F;
            const float* sB_l = sA_h + 2 * TILE_F;

            unsigned ah[4][4], bh[4][2], bl[4][2];
#pragma unroll
            for (int mt = 0; mt < 4; mt++) {
                int r0 = (mo + mt * 16 + gid) * HSTR + tig;
                ah[mt][0] = __float_as_uint(sA_h[r0]);
                ah[mt][1] = __float_as_uint(sA_h[r0 + 8 * HSTR]);
                ah[mt][2] = __float_as_uint(sA_h[r0 + 4]);
                ah[mt][3] = __float_as_uint(sA_h[r0 + 8 * HSTR + 4]);
            }
#pragma unroll
            for (int nt = 0; nt < 4; nt++) {
                int n0 = (no + nt * 8 + gid) * HSTR + tig;
                bh[nt][0] = __float_as_uint(sB_h[n0]);
                bh[nt][1] = __float_as_uint(sB_h[n0 + 4]);
                bl[nt][0] = __float_as_uint(sB_l[n0]);
                bl[nt][1] = __float_as_uint(sB_l[n0 + 4]);
            }
#pragma unroll
            for (int mt = 0; mt < 4; mt++)
#pragma unroll
                for (int nt = 0; nt < 4; nt++) {
                    mma_tf32(c[mt][nt], ah[mt], bh[nt]);
                    mma_tf32(c[mt][nt], ah[mt], bl[nt]);
                }
        }

        if (kt + 1 < nk) {
            sts_a(1 - p, ra0, lrow);
            sts_a(1 - p, ra1, lrow + 64);
            sts_b(1 - p, rb0, lrow);
            sts_b(1 - p, rb1, lrow + 64);
        }
        __syncthreads();
        p ^= 1;
    }

#pragma unroll
    for (int nt = 0; nt < 4; nt++) {
        int col = bx * 128 + no + nt * 8 + tig * 2;
        float bv0 = bias[col], bv1 = bias[col + 1];
#pragma unroll
        for (int mt = 0; mt < 4; mt++) {
            int row0 = by * 128 + mo + mt * 16 + gid;
            float2 v0 = make_float2(c[mt][nt][0] + bv0, c[mt][nt][1] + bv1);
            float2 v1 = make_float2(c[mt][nt][2] + bv0, c[mt][nt][3] + bv1);
            *(float2*)(C + (size_t)row0 * N + col) = v0;
            *(float2*)(C + (size_t)(row0 + 8) * N + col) = v1;
        }
    }
}

// ---------------- grid barrier helpers ---------------------------------------
__device__ __forceinline__ unsigned int ld_acq(const unsigned int* p) {
    unsigned int v;
    asm volatile("ld.acquire.gpu.global.u32 %0, [%1];" : "=r"(v) : "l"(p));
    return v;
}
__device__ __forceinline__ void grid_sync(unsigned int* cnt, unsigned int target) {
    __syncthreads();
    if (threadIdx.x == 0) {
        asm volatile("red.release.gpu.global.add.u32 [%0], %1;" :: "l"(cnt), "r"(1u));
        unsigned int guard = 0;
        while (ld_acq(cnt) < target) {
            __nanosleep(32);
            if (++guard > 30000000u) break;
        }
    }
    __syncthreads();
}

__global__ void reset_sync(unsigned int* p) { p[0] = 0; p[1] = 0; p[2] = 0; p[3] = 0; }

// ---------------- persistent bidirectional LSTM recurrence (bf16 mma) ---------
// R14 structure + two latency attacks:
// (a) PRODUCER-SIDE SPLIT: epilogue writes h's bf16 hi/lo u16 into gmem planes
//     (g_hhi/g_hlo); consumer staging = 8 LDG.128 + 8 STS.128, ZERO cvt — the
//     u32 words are already the packed (k,k+1) pairs the mma fragments load.
// (b) 512 THREADS, K-SPLIT mma: warps 0-7 do kt 0-15, warps 8-15 do kt 16-31
//     (fragment ptrs +128 words; bank pattern unchanged, 128 % 32 == 0).
//     Two cs buffers; epilogue (tid<256) adds both. 4 warps/SMSP.
// Staging map: thread = (lb = tid>>4, q = tid&15); uint4 index q + it*16 per
//   plane -> LDG coalesced (16 consecutive uint4), STS.128 conflict-free
//   (lanes 0-7 hit 32 distinct bank-quads at q*4 mod 32).
// Epilogue/barrier/prefetch identical to R13/R14 (3 passing rounds).
#define RWP 260
#define LSTM_SMEM ((4 * 32 * RWP + 2 * 32 * 33) * 4)   // 141568 B

__device__ __forceinline__ float sigmoidf(float x) { return 1.f / (1.f + expf(-x)); }

__global__ __launch_bounds__(512) void lstm_persist(
    const float* __restrict__ xg0, const float* __restrict__ xg1,
    const float* __restrict__ Whh0, const float* __restrict__ Whh1,
    float* __restrict__ seq,   // [B*T, 1024]: fwd cols 0..511, bwd 512..1023
    float* __restrict__ avg,   // [B, 1024] or nullptr
    unsigned int* __restrict__ sync_base)
{
    extern __shared__ unsigned smw[];
    unsigned* whiu = smw;                    // [32 col][260 w]
    unsigned* wlou = smw + 32 * RWP;
    unsigned* hhiu = smw + 2 * 32 * RWP;     // [32 b][260 w]
    unsigned* hlou = smw + 3 * 32 * RWP;
    float*    cs0  = (float*)(smw + 4 * 32 * RWP);   // [32][33]
    float*    cs1  = cs0 + 32 * 33;

    const int tid  = threadIdx.x;
    const int dir  = blockIdx.y;
    const int lane = tid & 31;
    const int warp = tid >> 5;               // 0..15
    const int jbase = blockIdx.x << 3;
    unsigned int* sync_cnt = sync_base + dir;

    // One-time: split W into bf16 hi/lo. col = jl*4 + gate.
    const float* whh = dir ? Whh1 : Whh0;
    for (int idx = tid; idx < 32 * 128; idx += 512) {
        int col = idx >> 7;
        int q   = idx & 127;
        int jl = col >> 2, gate = col & 3;
        float4 v = ((const float4*)(whh + (size_t)(gate * 512 + jbase + jl) * 512))[q];
        unsigned short h0, l0, h1, l1, h2, l2, h3, l3;
        split_bf16(v.x, h0, l0); split_bf16(v.y, h1, l1);
        split_bf16(v.z, h2, l2); split_bf16(v.w, h3, l3);
        int w = col * RWP + 2 * q;
        whiu[w]     = (unsigned)h0 | ((unsigned)h1 << 16);
        whiu[w + 1] = (unsigned)h2 | ((unsigned)h3 << 16);
        wlou[w]     = (unsigned)l0 | ((unsigned)l1 << 16);
        wlou[w + 1] = (unsigned)l2 | ((unsigned)l3 << 16);
    }
    // zero h hi/lo for step 0
    for (int i = tid; i < 2 * 32 * RWP; i += 512) hhiu[i] = 0u;

    const float* xg = dir ? xg1 : xg0;
    const unsigned int nb = gridDim.x;          // 64 CTAs per direction
    unsigned int target = 0;

    // gmem bf16 scratch planes for this direction
    unsigned short* shi = &g_hhi[dir][0][0][0];
    unsigned short* slo = &g_hlo[dir][0][0][0];

    // epilogue identity (meaningful for tid < 256): b = tid>>3, jl = tid&7
    const int eb = tid >> 3;
    const int ej = jbase + (tid & 7);
    float cstate = 0.f;
    float hsum = 0.f;

    // xg prefetch for step 0
    float pxi = 0.f, pxf = 0.f, pxg = 0.f, pxo = 0.f;
    if (tid < 256) {
        int t0 = dir ? (Tlen - 1) : 0;
        int bs = (eb * Tlen + t0) * 2048;
        pxi = xg[bs + ej];        pxf = xg[bs + 512 + ej];
        pxg = xg[bs + 1024 + ej]; pxo = xg[bs + 1536 + ej];
    }

    // mma fragment base pointers (constant across steps)
    const int w8   = warp & 7;
    const int kseg = warp >> 3;              // 0: kt 0-15, 1: kt 16-31
    const int mi = w8 >> 2, ni = w8 & 3;
    const int qr = lane >> 2, qc = lane & 3;
    const unsigned* Ah = hhiu + (mi * 16 + qr) * RWP + qc + kseg * 128;
    const unsigned* Al = hlou + (mi * 16 + qr) * RWP + qc + kseg * 128;
    const unsigned* Bh = whiu + (ni * 8 + qr) * RWP + qc + kseg * 128;
    const unsigned* Bl = wlou + (ni * 8 + qr) * RWP + qc + kseg * 128;
    float* csw = kseg ? cs1 : cs0;

    for (int s = 0; s < Tlen; ++s) {
        const int tcur = dir ? (Tlen - 1 - s) : s;

        if (s > 0) {
            const int tprev = dir ? (tcur + 1) : (tcur - 1);
            const int lb = tid >> 4;             // 0..31 batch
            const int q  = tid & 15;             // uint4 slot
            const uint4* ph = (const uint4*)(shi + ((size_t)tprev * Bsz + lb) * 512);
            const uint4* pl = (const uint4*)(slo + ((size_t)tprev * Bsz + lb) * 512);
#pragma unroll
            for (int it = 0; it < 4; ++it) {
                uint4 vh = ph[q + it * 16];
                uint4 vl = pl[q + it * 16];
                *(uint4*)&hhiu[lb * RWP + q * 4 + it * 64] = vh;
                *(uint4*)&hlou[lb * RWP + q * 4 + it * 64] = vl;
            }
        }
        __syncthreads();

        // tensor-core matvec: warp tile 16x8, 16 kt of k16 per warp, 3-term bf16
        float cc[4] = {0.f, 0.f, 0.f, 0.f};
#pragma unroll 4
        for (int kt = 0; kt < 16; ++kt) {
            const int o = kt * 8;
            unsigned ah[4], al[4], bh[2], bl[2];
            ah[0] = Ah[o];            ah[1] = Ah[o + 8 * RWP];
            ah[2] = Ah[o + 4];        ah[3] = Ah[o + 8 * RWP + 4];
            al[0] = Al[o];            al[1] = Al[o + 8 * RWP];
            al[2] = Al[o + 4];        al[3] = Al[o + 8 * RWP + 4];
            bh[0] = Bh[o];            bh[1] = Bh[o + 4];
            bl[0] = Bl[o];            bl[1] = Bl[o + 4];
            mma_bf16(cc, ah, bh);
            mma_bf16(cc, ah, bl);
            mma_bf16(cc, al, bh);
        }
        // store C fragments to this k-segment's cs buffer
        {
            int r0 = mi * 16 + qr;
            int nc = ni * 8 + 2 * qc;
            csw[r0 * 33 + nc]           = cc[0];
            csw[r0 * 33 + nc + 1]       = cc[1];
            csw[(r0 + 8) * 33 + nc]     = cc[2];
            csw[(r0 + 8) * 33 + nc + 1] = cc[3];
        }
        __syncthreads();

        // epilogue: thread (eb, ej), tid < 256
        if (tid < 256) {
            int base = eb * 33 + (tid & 7) * 4;
            float gi = cs0[base + 0] + cs1[base + 0] + pxi;
            float gf = cs0[base + 1] + cs1[base + 1] + pxf;
            float gg = cs0[base + 2] + cs1[base + 2] + pxg;
            float go = cs0[base + 3] + cs1[base + 3] + pxo;
            cstate = sigmoidf(gf) * cstate + sigmoidf(gi) * tanhf(gg);
            float h = sigmoidf(go) * tanhf(cstate);
            seq[(size_t)(eb * Tlen + tcur) * 1024 + dir * 512 + ej] = h;
            hsum += h;
            // producer-side bf16 split -> gmem planes (consumed next step)
            unsigned short hh, hl;
            split_bf16(h, hh, hl);
            size_t si = ((size_t)tcur * Bsz + eb) * 512 + ej;
            shi[si] = hh;
            slo[si] = hl;
        }

        if (s + 1 < Tlen) {
            if (tid < 256) {
                int tn = dir ? (tcur - 1) : (tcur + 1);
                int bs = (eb * Tlen + tn) * 2048;
                pxi = xg[bs + ej];        pxf = xg[bs + 512 + ej];
                pxg = xg[bs + 1024 + ej]; pxo = xg[bs + 1536 + ej];
            }
            target += nb;
            grid_sync(sync_cnt, target);   // orders scratch stores before loads
        }
    }

    if (avg && tid < 256) avg[eb * 1024 + dir * 512 + ej] = hsum * (1.f / Tlen);
}

// ---------------- launch ------------------------------------------------------
extern "C" void kernel_launch(void* const* d_in, const int* in_sizes, int n_in,
                              void* d_out, int out_size)
{
    const float* x     = (const float*)d_in[0];
    const float* Wih0f = (const float*)d_in[1];
    const float* Whh0f = (const float*)d_in[2];
    const float* b0f   = (const float*)d_in[3];
    const float* Wih0b = (const float*)d_in[4];
    const float* Whh0b = (const float*)d_in[5];
    const float* b0b   = (const float*)d_in[6];
    const float* Wih1f = (const float*)d_in[7];
    const float* Whh1f = (const float*)d_in[8];
    const float* b1f   = (const float*)d_in[9];
    const float* Wih1b = (const float*)d_in[10];
    const float* Whh1b = (const float*)d_in[11];
    const float* b1b   = (const float*)d_in[12];

    float* avg    = (float*)d_out;
    float* outseq = avg + Bsz * 2 * Hd;   // avg_out first, then out [B,T,1024]

    float *xg0, *xg1, *x1;
    unsigned int* syncp;
    cudaGetSymbolAddress((void**)&xg0, g_xg0);
    cudaGetSymbolAddress((void**)&xg1, g_xg1);
    cudaGetSymbolAddress((void**)&x1,  g_x1);
    cudaGetSymbolAddress((void**)&syncp, g_sync);

    cudaFuncSetAttribute(lstm_persist, cudaFuncAttributeMaxDynamicSharedMemorySize, LSTM_SMEM);
    cudaFuncSetAttribute(tf32_gemm_bias, cudaFuncAttributeMaxDynamicSharedMemorySize, GEMM_SMEM);

    dim3 gemm_grid(2048 / 128, 16384 / 128);     // (16, 128)
    dim3 step_grid(64, 2);

    reset_sync<<<1, 1>>>(syncp);

    // Layer 0 input gates (tensor cores, tf32 2-term split)
    tf32_gemm_bias<<<gemm_grid, 256, GEMM_SMEM>>>(x, Wih0f, b0f, xg0, 16384, 2048, 512);
    tf32_gemm_bias<<<gemm_grid, 256, GEMM_SMEM>>>(x, Wih0b, b0b, xg1, 16384, 2048, 512);
    // Layer 0 recurrence (persistent bf16 tensor-core, counters 0,1)
    lstm_persist<<<step_grid, 512, LSTM_SMEM>>>(xg0, xg1, Whh0f, Whh0b, x1, nullptr, syncp);
    // Layer 1 input gates (K = 1024)
    tf32_gemm_bias<<<gemm_grid, 256, GEMM_SMEM>>>(x1, Wih1f, b1f, xg0, 16384, 2048, 1024);
    tf32_gemm_bias<<<gemm_grid, 256, GEMM_SMEM>>>(x1, Wih1b, b1b, xg1, 16384, 2048, 1024);
    // Layer 1 recurrence -> out region of d_out, mean fused (counters 2,3)
    lstm_persist<<<step_grid, 512, LSTM_SMEM>>>(xg0, xg1, Whh1f, Whh1b, outseq, avg, syncp + 2);
}

// round 16
// speedup vs baseline: 2.0832x; 1.0124x over previous
#include <cuda_runtime.h>
#include <cuda_bf16.h>
#include <math.h>

#define Bsz 32
#define Tlen 512
#define Hd 512

// ---------------- scratch (static device globals per harness rules) ----------
__device__ float g_xg0[(size_t)Bsz * Tlen * 4 * Hd];   // 134 MB  (dir 0 gates)
__device__ float g_xg1[(size_t)Bsz * Tlen * 4 * Hd];   // 134 MB  (dir 1 gates)
__device__ float g_x1[(size_t)Bsz * Tlen * 2 * Hd];    // 64 MB   (layer-0 output)
__device__ unsigned short g_hhi[2][Tlen][Bsz][512];    // 32 MB  (h bf16 hi plane)
__device__ unsigned short g_hlo[2][Tlen][Bsz][512];    // 32 MB  (h bf16 lo plane)
__device__ unsigned int g_sync[4];                     // per-layer, per-dir barriers

// ---------------- bf16 helpers -------------------------------------------------
__device__ __forceinline__ void mma_bf16(float* c, const unsigned* a, const unsigned* b) {
    asm volatile(
        "mma.sync.aligned.m16n8k16.row.col.f32.bf16.bf16.f32 "
        "{%0,%1,%2,%3}, {%4,%5,%6,%7}, {%8,%9}, {%0,%1,%2,%3};"
        : "+f"(c[0]), "+f"(c[1]), "+f"(c[2]), "+f"(c[3])
        : "r"(a[0]), "r"(a[1]), "r"(a[2]), "r"(a[3]), "r"(b[0]), "r"(b[1]));
}
__device__ __forceinline__ void split_bf16(float f, unsigned short& h, unsigned short& l) {
    __nv_bfloat16 bh = __float2bfloat16_rn(f);
    float fh = __bfloat162float(bh);
    __nv_bfloat16 bl = __float2bfloat16_rn(f - fh);
    h = __bfloat16_as_ushort(bh);
    l = __bfloat16_as_ushort(bl);
}

// ---------------- BF16 3-term split GEMM: C = A*W^T + bias --------------------
// C ≈ AhiBhi + AhiBlo + AloBhi (dropped AloBlo ~2^-16 relative).
// CTA tile 128x128, k-step 16, 8 warps (2x4), warp tile 64x32.
// Per buffer, 4 planes of packed bf16-pair words [128 rows][pitch 12]:
// AH, AL, BH, BL (1536 words each). Fragment pattern 12r+c covers 32 banks.
#define WPITCH 12
#define PLANE_W (128 * WPITCH)          // 1536 words
#define BUF_W   (4 * PLANE_W)           // 6144 words
#define GEMM_SMEM (2 * BUF_W * 4)       // 49152 bytes

__global__ __launch_bounds__(256) void bf16_gemm_bias(
    const float* __restrict__ A, const float* __restrict__ W,
    const float* __restrict__ bias, float* __restrict__ C,
    int M, int N, int K)
{
    extern __shared__ unsigned smu[];
    const int tid  = threadIdx.x;
    const int lane = tid & 31;
    const int warp = tid >> 5;
    const int qr   = lane >> 2;
    const int qc   = lane & 3;
    const int bx = blockIdx.x, by = blockIdx.y;
    const int mo = (warp >> 2) * 64;
    const int no = (warp & 3) * 32;

    // loader: lrow 0..63 (two row-halves), lkq in {0,4,8,12}
    const int lrow = tid >> 2;
    const int lkq  = (tid & 3) << 2;

    const float* Ag0 = A + (size_t)(by * 128 + lrow) * K + lkq;
    const float* Ag1 = A + (size_t)(by * 128 + lrow + 64) * K + lkq;
    const float* Wg0 = W + (size_t)(bx * 128 + lrow) * K + lkq;
    const float* Wg1 = W + (size_t)(bx * 128 + lrow + 64) * K + lkq;

    float c[4][4][4];
#pragma unroll
    for (int mt = 0; mt < 4; mt++)
#pragma unroll
        for (int nt = 0; nt < 4; nt++)
#pragma unroll
            for (int i = 0; i < 4; i++) c[mt][nt][i] = 0.f;

    const int nk = K >> 4;
    float4 ra0, ra1, rb0, rb1;

    ra0 = *(const float4*)Ag0; ra1 = *(const float4*)Ag1;
    rb0 = *(const float4*)Wg0; rb1 = *(const float4*)Wg1;

    // split float4 into hi/lo packed-pair words at plane[row][lkq/2 .. +1]
    auto sts_plane = [&](unsigned* baseH, unsigned* baseL, float4 v, int row) {
        unsigned short hx, lx, hy, ly, hz, lz, hw, lw;
        split_bf16(v.x, hx, lx); split_bf16(v.y, hy, ly);
        split_bf16(v.z, hz, lz); split_bf16(v.w, hw, lw);
        int w = row * WPITCH + (lkq >> 1);
        baseH[w]     = (unsigned)hx | ((unsigned)hy << 16);
        baseH[w + 1] = (unsigned)hz | ((unsigned)hw << 16);
        baseL[w]     = (unsigned)lx | ((unsigned)ly << 16);
        baseL[w + 1] = (unsigned)lz | ((unsigned)lw << 16);
    };
    auto sts_all = [&](int p) {
        unsigned* AH = smu + p * BUF_W;
        unsigned* AL = AH + PLANE_W;
        unsigned* BH = AH + 2 * PLANE_W;
        unsigned* BL = AH + 3 * PLANE_W;
        sts_plane(AH, AL, ra0, lrow);
        sts_plane(AH, AL, ra1, lrow + 64);
        sts_plane(BH, BL, rb0, lrow);
        sts_plane(BH, BL, rb1, lrow + 64);
    };

    sts_all(0);
    __syncthreads();

    int p = 0;
    for (int kt = 0; kt < nk; ++kt) {
        if (kt + 1 < nk) {
            const int k0 = (kt + 1) << 4;
            ra0 = *(const float4*)(Ag0 + k0); ra1 = *(const float4*)(Ag1 + k0);
            rb0 = *(const float4*)(Wg0 + k0); rb1 = *(const float4*)(Wg1 + k0);
        }

        {
            const unsigned* AH = smu + p * BUF_W;
            const unsigned* AL = AH + PLANE_W;
            const unsigned* BH = AH + 2 * PLANE_W;
            const unsigned* BL = AH + 3 * PLANE_W;

            unsigned ah[4][4], al[4][4], bh[4][2], bl[4][2];
#pragma unroll
            for (int mt = 0; mt < 4; mt++) {
                int r0 = (mo + mt * 16 + qr) * WPITCH + qc;
                ah[mt][0] = AH[r0];
                ah[mt][1] = AH[r0 + 8 * WPITCH];
                ah[mt][2] = AH[r0 + 4];
                ah[mt][3] = AH[r0 + 8 * WPITCH + 4];
                al[mt][0] = AL[r0];
                al[mt][1] = AL[r0 + 8 * WPITCH];
                al[mt][2] = AL[r0 + 4];
                al[mt][3] = AL[r0 + 8 * WPITCH + 4];
            }
#pragma unroll
            for (int nt = 0; nt < 4; nt++) {
                int n0 = (no + nt * 8 + qr) * WPITCH + qc;
                bh[nt][0] = BH[n0];
                bh[nt][1] = BH[n0 + 4];
                bl[nt][0] = BL[n0];
                bl[nt][1] = BL[n0 + 4];
            }
#pragma unroll
            for (int mt = 0; mt < 4; mt++)
#pragma unroll
                for (int nt = 0; nt < 4; nt++) {
                    mma_bf16(c[mt][nt], ah[mt], bh[nt]);
                    mma_bf16(c[mt][nt], ah[mt], bl[nt]);
                    mma_bf16(c[mt][nt], al[mt], bh[nt]);
                }
        }

        if (kt + 1 < nk) {
            sts_all(1 - p);
        }
        __syncthreads();
        p ^= 1;
    }

#pragma unroll
    for (int nt = 0; nt < 4; nt++) {
        int col = bx * 128 + no + nt * 8 + qc * 2;
        float bv0 = bias[col], bv1 = bias[col + 1];
#pragma unroll
        for (int mt = 0; mt < 4; mt++) {
            int row0 = by * 128 + mo + mt * 16 + qr;
            float2 v0 = make_float2(c[mt][nt][0] + bv0, c[mt][nt][1] + bv1);
            float2 v1 = make_float2(c[mt][nt][2] + bv0, c[mt][nt][3] + bv1);
            *(float2*)(C + (size_t)row0 * N + col) = v0;
            *(float2*)(C + (size_t)(row0 + 8) * N + col) = v1;
        }
    }
}

// ---------------- grid barrier helpers ---------------------------------------
__device__ __forceinline__ unsigned int ld_acq(const unsigned int* p) {
    unsigned int v;
    asm volatile("ld.acquire.gpu.global.u32 %0, [%1];" : "=r"(v) : "l"(p));
    return v;
}
__device__ __forceinline__ void grid_sync(unsigned int* cnt, unsigned int target) {
    __syncthreads();
    if (threadIdx.x == 0) {
        asm volatile("red.release.gpu.global.add.u32 [%0], %1;" :: "l"(cnt), "r"(1u));
        unsigned int guard = 0;
        while (ld_acq(cnt) < target) {
            __nanosleep(32);
            if (++guard > 30000000u) break;
        }
    }
    __syncthreads();
}

__global__ void reset_sync(unsigned int* p) { p[0] = 0; p[1] = 0; p[2] = 0; p[3] = 0; }

// ---------------- persistent bidirectional LSTM recurrence (bf16 mma) ---------
// R15 winner, verbatim: producer-side bf16 split to gmem planes, 512 threads,
// K-split mma (warps 0-7 kt 0-15, warps 8-15 kt 16-31), two cs buffers.
#define RWP 260
#define LSTM_SMEM ((4 * 32 * RWP + 2 * 32 * 33) * 4)   // 141568 B

__device__ __forceinline__ float sigmoidf(float x) { return 1.f / (1.f + expf(-x)); }

__global__ __launch_bounds__(512) void lstm_persist(
    const float* __restrict__ xg0, const float* __restrict__ xg1,
    const float* __restrict__ Whh0, const float* __restrict__ Whh1,
    float* __restrict__ seq,   // [B*T, 1024]: fwd cols 0..511, bwd 512..1023
    float* __restrict__ avg,   // [B, 1024] or nullptr
    unsigned int* __restrict__ sync_base)
{
    extern __shared__ unsigned smw[];
    unsigned* whiu = smw;                    // [32 col][260 w]
    unsigned* wlou = smw + 32 * RWP;
    unsigned* hhiu = smw + 2 * 32 * RWP;     // [32 b][260 w]
    unsigned* hlou = smw + 3 * 32 * RWP;
    float*    cs0  = (float*)(smw + 4 * 32 * RWP);   // [32][33]
    float*    cs1  = cs0 + 32 * 33;

    const int tid  = threadIdx.x;
    const int dir  = blockIdx.y;
    const int lane = tid & 31;
    const int warp = tid >> 5;               // 0..15
    const int jbase = blockIdx.x << 3;
    unsigned int* sync_cnt = sync_base + dir;

    // One-time: split W into bf16 hi/lo. col = jl*4 + gate.
    const float* whh = dir ? Whh1 : Whh0;
    for (int idx = tid; idx < 32 * 128; idx += 512) {
        int col = idx >> 7;
        int q   = idx & 127;
        int jl = col >> 2, gate = col & 3;
        float4 v = ((const float4*)(whh + (size_t)(gate * 512 + jbase + jl) * 512))[q];
        unsigned short h0, l0, h1, l1, h2, l2, h3, l3;
        split_bf16(v.x, h0, l0); split_bf16(v.y, h1, l1);
        split_bf16(v.z, h2, l2); split_bf16(v.w, h3, l3);
        int w = col * RWP + 2 * q;
        whiu[w]     = (unsigned)h0 | ((unsigned)h1 << 16);
        whiu[w + 1] = (unsigned)h2 | ((unsigned)h3 << 16);
        wlou[w]     = (unsigned)l0 | ((unsigned)l1 << 16);
        wlou[w + 1] = (unsigned)l2 | ((unsigned)l3 << 16);
    }
    // zero h hi/lo for step 0
    for (int i = tid; i < 2 * 32 * RWP; i += 512) hhiu[i] = 0u;

    const float* xg = dir ? xg1 : xg0;
    const unsigned int nb = gridDim.x;          // 64 CTAs per direction
    unsigned int target = 0;

    unsigned short* shi = &g_hhi[dir][0][0][0];
    unsigned short* slo = &g_hlo[dir][0][0][0];

    const int eb = tid >> 3;
    const int ej = jbase + (tid & 7);
    float cstate = 0.f;
    float hsum = 0.f;

    float pxi = 0.f, pxf = 0.f, pxg = 0.f, pxo = 0.f;
    if (tid < 256) {
        int t0 = dir ? (Tlen - 1) : 0;
        int bs = (eb * Tlen + t0) * 2048;
        pxi = xg[bs + ej];        pxf = xg[bs + 512 + ej];
        pxg = xg[bs + 1024 + ej]; pxo = xg[bs + 1536 + ej];
    }

    const int w8   = warp & 7;
    const int kseg = warp >> 3;              // 0: kt 0-15, 1: kt 16-31
    const int mi = w8 >> 2, ni = w8 & 3;
    const int qr = lane >> 2, qc = lane & 3;
    const unsigned* Ah = hhiu + (mi * 16 + qr) * RWP + qc + kseg * 128;
    const unsigned* Al = hlou + (mi * 16 + qr) * RWP + qc + kseg * 128;
    const unsigned* Bh = whiu + (ni * 8 + qr) * RWP + qc + kseg * 128;
    const unsigned* Bl = wlou + (ni * 8 + qr) * RWP + qc + kseg * 128;
    float* csw = kseg ? cs1 : cs0;

    for (int s = 0; s < Tlen; ++s) {
        const int tcur = dir ? (Tlen - 1 - s) : s;

        if (s > 0) {
            const int tprev = dir ? (tcur + 1) : (tcur - 1);
            const int lb = tid >> 4;             // 0..31 batch
            const int q  = tid & 15;             // uint4 slot
            const uint4* ph = (const uint4*)(shi + ((size_t)tprev * Bsz + lb) * 512);
            const uint4* pl = (const uint4*)(slo + ((size_t)tprev * Bsz + lb) * 512);
#pragma unroll
            for (int it = 0; it < 4; ++it) {
                uint4 vh = ph[q + it * 16];
                uint4 vl = pl[q + it * 16];
                *(uint4*)&hhiu[lb * RWP + q * 4 + it * 64] = vh;
                *(uint4*)&hlou[lb * RWP + q * 4 + it * 64] = vl;
            }
        }
        __syncthreads();

        float cc[4] = {0.f, 0.f, 0.f, 0.f};
#pragma unroll 4
        for (int kt = 0; kt < 16; ++kt) {
            const int o = kt * 8;
            unsigned ah[4], al[4], bh[2], bl[2];
            ah[0] = Ah[o];            ah[1] = Ah[o + 8 * RWP];
            ah[2] = Ah[o + 4];        ah[3] = Ah[o + 8 * RWP + 4];
            al[0] = Al[o];            al[1] = Al[o + 8 * RWP];
            al[2] = Al[o + 4];        al[3] = Al[o + 8 * RWP + 4];
            bh[0] = Bh[o];            bh[1] = Bh[o + 4];
            bl[0] = Bl[o];            bl[1] = Bl[o + 4];
            mma_bf16(cc, ah, bh);
            mma_bf16(cc, ah, bl);
            mma_bf16(cc, al, bh);
        }
        {
            int r0 = mi * 16 + qr;
            int nc = ni * 8 + 2 * qc;
            csw[r0 * 33 + nc]           = cc[0];
            csw[r0 * 33 + nc + 1]       = cc[1];
            csw[(r0 + 8) * 33 + nc]     = cc[2];
            csw[(r0 + 8) * 33 + nc + 1] = cc[3];
        }
        __syncthreads();

        if (tid < 256) {
            int base = eb * 33 + (tid & 7) * 4;
            float gi = cs0[base + 0] + cs1[base + 0] + pxi;
            float gf = cs0[base + 1] + cs1[base + 1] + pxf;
            float gg = cs0[base + 2] + cs1[base + 2] + pxg;
            float go = cs0[base + 3] + cs1[base + 3] + pxo;
            cstate = sigmoidf(gf) * cstate + sigmoidf(gi) * tanhf(gg);
            float h = sigmoidf(go) * tanhf(cstate);
            seq[(size_t)(eb * Tlen + tcur) * 1024 + dir * 512 + ej] = h;
            hsum += h;
            unsigned short hh, hl;
            split_bf16(h, hh, hl);
            size_t si = ((size_t)tcur * Bsz + eb) * 512 + ej;
            shi[si] = hh;
            slo[si] = hl;
        }

        if (s + 1 < Tlen) {
            if (tid < 256) {
                int tn = dir ? (tcur - 1) : (tcur + 1);
                int bs = (eb * Tlen + tn) * 2048;
                pxi = xg[bs + ej];        pxf = xg[bs + 512 + ej];
                pxg = xg[bs + 1024 + ej]; pxo = xg[bs + 1536 + ej];
            }
            target += nb;
            grid_sync(sync_cnt, target);
        }
    }

    if (avg && tid < 256) avg[eb * 1024 + dir * 512 + ej] = hsum * (1.f / Tlen);
}

// ---------------- launch ------------------------------------------------------
extern "C" void kernel_launch(void* const* d_in, const int* in_sizes, int n_in,
                              void* d_out, int out_size)
{
    const float* x     = (const float*)d_in[0];
    const float* Wih0f = (const float*)d_in[1];
    const float* Whh0f = (const float*)d_in[2];
    const float* b0f   = (const float*)d_in[3];
    const float* Wih0b = (const float*)d_in[4];
    const float* Whh0b = (const float*)d_in[5];
    const float* b0b   = (const float*)d_in[6];
    const float* Wih1f = (const float*)d_in[7];
    const float* Whh1f = (const float*)d_in[8];
    const float* b1f   = (const float*)d_in[9];
    const float* Wih1b = (const float*)d_in[10];
    const float* Whh1b = (const float*)d_in[11];
    const float* b1b   = (const float*)d_in[12];

    float* avg    = (float*)d_out;
    float* outseq = avg + Bsz * 2 * Hd;   // avg_out first, then out [B,T,1024]

    float *xg0, *xg1, *x1;
    unsigned int* syncp;
    cudaGetSymbolAddress((void**)&xg0, g_xg0);
    cudaGetSymbolAddress((void**)&xg1, g_xg1);
    cudaGetSymbolAddress((void**)&x1,  g_x1);
    cudaGetSymbolAddress((void**)&syncp, g_sync);

    cudaFuncSetAttribute(lstm_persist, cudaFuncAttributeMaxDynamicSharedMemorySize, LSTM_SMEM);
    cudaFuncSetAttribute(bf16_gemm_bias, cudaFuncAttributeMaxDynamicSharedMemorySize, GEMM_SMEM);

    dim3 gemm_grid(2048 / 128, 16384 / 128);     // (16, 128)
    dim3 step_grid(64, 2);

    reset_sync<<<1, 1>>>(syncp);

    // Layer 0 input gates (bf16 3-term split, tensor cores)
    bf16_gemm_bias<<<gemm_grid, 256, GEMM_SMEM>>>(x, Wih0f, b0f, xg0, 16384, 2048, 512);
    bf16_gemm_bias<<<gemm_grid, 256, GEMM_SMEM>>>(x, Wih0b, b0b, xg1, 16384, 2048, 512);
    // Layer 0 recurrence (persistent bf16 tensor-core, counters 0,1)
    lstm_persist<<<step_grid, 512, LSTM_SMEM>>>(xg0, xg1, Whh0f, Whh0b, x1, nullptr, syncp);
    // Layer 1 input gates (K = 1024)
    bf16_gemm_bias<<<gemm_grid, 256, GEMM_SMEM>>>(x1, Wih1f, b1f, xg0, 16384, 2048, 1024);
    bf16_gemm_bias<<<gemm_grid, 256, GEMM_SMEM>>>(x1, Wih1b, b1b, xg1, 16384, 2048, 1024);
    // Layer 1 recurrence -> out region of d_out, mean fused (counters 2,3)
    lstm_persist<<<step_grid, 512, LSTM_SMEM>>>(xg0, xg1, Whh1f, Whh1b, outseq, avg, syncp + 2);
}

// round 17
// speedup vs baseline: 2.0837x; 1.0003x over previous
#include <cuda_runtime.h>
#include <cuda_bf16.h>
#include <math.h>

#define Bsz 32
#define Tlen 512
#define Hd 512

// ---------------- scratch (static device globals per harness rules) ----------
__device__ float g_xg0[(size_t)Bsz * Tlen * 4 * Hd];   // 134 MB  (dir 0 gates)
__device__ float g_xg1[(size_t)Bsz * Tlen * 4 * Hd];   // 134 MB  (dir 1 gates)
__device__ float g_x1[(size_t)Bsz * Tlen * 2 * Hd];    // 64 MB   (layer-0 output)
__device__ unsigned short g_hhi[2][Tlen][Bsz][512];    // 32 MB  (h bf16 hi plane)
__device__ unsigned short g_hlo[2][Tlen][Bsz][512];    // 32 MB  (h bf16 lo plane)
__device__ unsigned int g_sync[4];                     // per-layer, per-dir barriers

// ---------------- bf16 helpers -------------------------------------------------
__device__ __forceinline__ void mma_bf16(float* c, const unsigned* a, const unsigned* b) {
    asm volatile(
        "mma.sync.aligned.m16n8k16.row.col.f32.bf16.bf16.f32 "
        "{%0,%1,%2,%3}, {%4,%5,%6,%7}, {%8,%9}, {%0,%1,%2,%3};"
        : "+f"(c[0]), "+f"(c[1]), "+f"(c[2]), "+f"(c[3])
        : "r"(a[0]), "r"(a[1]), "r"(a[2]), "r"(a[3]), "r"(b[0]), "r"(b[1]));
}
__device__ __forceinline__ void split_bf16(float f, unsigned short& h, unsigned short& l) {
    __nv_bfloat16 bh = __float2bfloat16_rn(f);
    float fh = __bfloat162float(bh);
    __nv_bfloat16 bl = __float2bfloat16_rn(f - fh);
    h = __bfloat16_as_ushort(bh);
    l = __bfloat16_as_ushort(bl);
}

// ---------------- BF16 3-term split GEMM: C = A*W^T + bias --------------------
// C ≈ AhiBhi + AhiBlo + AloBhi (dropped AloBlo ~2^-16 relative).
// R17: 512 THREADS (16 warps, 4/SMSP), warp tile 64x16 (mo=(w>>3)*64,
// no=(w&7)*16). Loader: thread t loads exactly ONE float4 of A and one of W
// per k-iter (row = t>>2, kq = (t&3)*4). Fragment layout/pitch and 3-term mma
// recipe unchanged from the R16 winner. regs/thread ~90 -> no spills.
#define WPITCH 12
#define PLANE_W (128 * WPITCH)          // 1536 words
#define BUF_W   (4 * PLANE_W)           // 6144 words
#define GEMM_SMEM (2 * BUF_W * 4)       // 49152 bytes

__global__ __launch_bounds__(512) void bf16_gemm_bias(
    const float* __restrict__ A, const float* __restrict__ W,
    const float* __restrict__ bias, float* __restrict__ C,
    int M, int N, int K)
{
    extern __shared__ unsigned smu[];
    const int tid  = threadIdx.x;
    const int lane = tid & 31;
    const int warp = tid >> 5;          // 0..15
    const int qr   = lane >> 2;
    const int qc   = lane & 3;
    const int bx = blockIdx.x, by = blockIdx.y;
    const int mo = (warp >> 3) * 64;    // 0 or 64
    const int no = (warp & 7) * 16;     // 0..112

    // loader: row 0..127, kq in {0,4,8,12}
    const int lrow = tid >> 2;
    const int lkq  = (tid & 3) << 2;

    const float* Ag = A + (size_t)(by * 128 + lrow) * K + lkq;
    const float* Wg = W + (size_t)(bx * 128 + lrow) * K + lkq;

    float c[4][2][4];
#pragma unroll
    for (int mt = 0; mt < 4; mt++)
#pragma unroll
        for (int nt = 0; nt < 2; nt++)
#pragma unroll
            for (int i = 0; i < 4; i++) c[mt][nt][i] = 0.f;

    const int nk = K >> 4;
    float4 ra, rb;

    ra = *(const float4*)Ag;
    rb = *(const float4*)Wg;

    auto sts_plane = [&](unsigned* baseH, unsigned* baseL, float4 v) {
        unsigned short hx, lx, hy, ly, hz, lz, hw, lw;
        split_bf16(v.x, hx, lx); split_bf16(v.y, hy, ly);
        split_bf16(v.z, hz, lz); split_bf16(v.w, hw, lw);
        int w = lrow * WPITCH + (lkq >> 1);
        baseH[w]     = (unsigned)hx | ((unsigned)hy << 16);
        baseH[w + 1] = (unsigned)hz | ((unsigned)hw << 16);
        baseL[w]     = (unsigned)lx | ((unsigned)ly << 16);
        baseL[w + 1] = (unsigned)lz | ((unsigned)lw << 16);
    };
    auto sts_all = [&](int p) {
        unsigned* AH = smu + p * BUF_W;
        sts_plane(AH, AH + PLANE_W, ra);
        sts_plane(AH + 2 * PLANE_W, AH + 3 * PLANE_W, rb);
    };

    sts_all(0);
    __syncthreads();

    int p = 0;
    for (int kt = 0; kt < nk; ++kt) {
        if (kt + 1 < nk) {
            const int k0 = (kt + 1) << 4;
            ra = *(const float4*)(Ag + k0);
            rb = *(const float4*)(Wg + k0);
        }

        {
            const unsigned* AH = smu + p * BUF_W;
            const unsigned* AL = AH + PLANE_W;
            const unsigned* BH = AH + 2 * PLANE_W;
            const unsigned* BL = AH + 3 * PLANE_W;

            unsigned ah[4][4], al[4][4], bh[2][2], bl[2][2];
#pragma unroll
            for (int mt = 0; mt < 4; mt++) {
                int r0 = (mo + mt * 16 + qr) * WPITCH + qc;
                ah[mt][0] = AH[r0];
                ah[mt][1] = AH[r0 + 8 * WPITCH];
                ah[mt][2] = AH[r0 + 4];
                ah[mt][3] = AH[r0 + 8 * WPITCH + 4];
                al[mt][0] = AL[r0];
                al[mt][1] = AL[r0 + 8 * WPITCH];
                al[mt][2] = AL[r0 + 4];
                al[mt][3] = AL[r0 + 8 * WPITCH + 4];
            }
#pragma unroll
            for (int nt = 0; nt < 2; nt++) {
                int n0 = (no + nt * 8 + qr) * WPITCH + qc;
                bh[nt][0] = BH[n0];
                bh[nt][1] = BH[n0 + 4];
                bl[nt][0] = BL[n0];
                bl[nt][1] = BL[n0 + 4];
            }
#pragma unroll
            for (int mt = 0; mt < 4; mt++)
#pragma unroll
                for (int nt = 0; nt < 2; nt++) {
                    mma_bf16(c[mt][nt], ah[mt], bh[nt]);
                    mma_bf16(c[mt][nt], ah[mt], bl[nt]);
                    mma_bf16(c[mt][nt], al[mt], bh[nt]);
                }
        }

        if (kt + 1 < nk) {
            sts_all(1 - p);
        }
        __syncthreads();
        p ^= 1;
    }

#pragma unroll
    for (int nt = 0; nt < 2; nt++) {
        int col = bx * 128 + no + nt * 8 + qc * 2;
        float bv0 = bias[col], bv1 = bias[col + 1];
#pragma unroll
        for (int mt = 0; mt < 4; mt++) {
            int row0 = by * 128 + mo + mt * 16 + qr;
            float2 v0 = make_float2(c[mt][nt][0] + bv0, c[mt][nt][1] + bv1);
            float2 v1 = make_float2(c[mt][nt][2] + bv0, c[mt][nt][3] + bv1);
            *(float2*)(C + (size_t)row0 * N + col) = v0;
            *(float2*)(C + (size_t)(row0 + 8) * N + col) = v1;
        }
    }
}

// ---------------- grid barrier helpers ---------------------------------------
__device__ __forceinline__ unsigned int ld_acq(const unsigned int* p) {
    unsigned int v;
    asm volatile("ld.acquire.gpu.global.u32 %0, [%1];" : "=r"(v) : "l"(p));
    return v;
}
__device__ __forceinline__ void grid_sync(unsigned int* cnt, unsigned int target) {
    __syncthreads();
    if (threadIdx.x == 0) {
        asm volatile("red.release.gpu.global.add.u32 [%0], %1;" :: "l"(cnt), "r"(1u));
        unsigned int guard = 0;
        while (ld_acq(cnt) < target) {
            __nanosleep(32);
            if (++guard > 30000000u) break;
        }
    }
    __syncthreads();
}

__global__ void reset_sync(unsigned int* p) { p[0] = 0; p[1] = 0; p[2] = 0; p[3] = 0; }

// ---------------- persistent bidirectional LSTM recurrence (bf16 mma) ---------
// R15/R16 winner, verbatim.
#define RWP 260
#define LSTM_SMEM ((4 * 32 * RWP + 2 * 32 * 33) * 4)   // 141568 B

__device__ __forceinline__ float sigmoidf(float x) { return 1.f / (1.f + expf(-x)); }

__global__ __launch_bounds__(512) void lstm_persist(
    const float* __restrict__ xg0, const float* __restrict__ xg1,
    const float* __restrict__ Whh0, const float* __restrict__ Whh1,
    float* __restrict__ seq,   // [B*T, 1024]: fwd cols 0..511, bwd 512..1023
    float* __restrict__ avg,   // [B, 1024] or nullptr
    unsigned int* __restrict__ sync_base)
{
    extern __shared__ unsigned smw[];
    unsigned* whiu = smw;                    // [32 col][260 w]
    unsigned* wlou = smw + 32 * RWP;
    unsigned* hhiu = smw + 2 * 32 * RWP;     // [32 b][260 w]
    unsigned* hlou = smw + 3 * 32 * RWP;
    float*    cs0  = (float*)(smw + 4 * 32 * RWP);   // [32][33]
    float*    cs1  = cs0 + 32 * 33;

    const int tid  = threadIdx.x;
    const int dir  = blockIdx.y;
    const int lane = tid & 31;
    const int warp = tid >> 5;               // 0..15
    const int jbase = blockIdx.x << 3;
    unsigned int* sync_cnt = sync_base + dir;

    const float* whh = dir ? Whh1 : Whh0;
    for (int idx = tid; idx < 32 * 128; idx += 512) {
        int col = idx >> 7;
        int q   = idx & 127;
        int jl = col >> 2, gate = col & 3;
        float4 v = ((const float4*)(whh + (size_t)(gate * 512 + jbase + jl) * 512))[q];
        unsigned short h0, l0, h1, l1, h2, l2, h3, l3;
        split_bf16(v.x, h0, l0); split_bf16(v.y, h1, l1);
        split_bf16(v.z, h2, l2); split_bf16(v.w, h3, l3);
        int w = col * RWP + 2 * q;
        whiu[w]     = (unsigned)h0 | ((unsigned)h1 << 16);
        whiu[w + 1] = (unsigned)h2 | ((unsigned)h3 << 16);
        wlou[w]     = (unsigned)l0 | ((unsigned)l1 << 16);
        wlou[w + 1] = (unsigned)l2 | ((unsigned)l3 << 16);
    }
    for (int i = tid; i < 2 * 32 * RWP; i += 512) hhiu[i] = 0u;

    const float* xg = dir ? xg1 : xg0;
    const unsigned int nb = gridDim.x;          // 64 CTAs per direction
    unsigned int target = 0;

    unsigned short* shi = &g_hhi[dir][0][0][0];
    unsigned short* slo = &g_hlo[dir][0][0][0];

    const int eb = tid >> 3;
    const int ej = jbase + (tid & 7);
    float cstate = 0.f;
    float hsum = 0.f;

    float pxi = 0.f, pxf = 0.f, pxg = 0.f, pxo = 0.f;
    if (tid < 256) {
        int t0 = dir ? (Tlen - 1) : 0;
        int bs = (eb * Tlen + t0) * 2048;
        pxi = xg[bs + ej];        pxf = xg[bs + 512 + ej];
        pxg = xg[bs + 1024 + ej]; pxo = xg[bs + 1536 + ej];
    }

    const int w8   = warp & 7;
    const int kseg = warp >> 3;              // 0: kt 0-15, 1: kt 16-31
    const int mi = w8 >> 2, ni = w8 & 3;
    const int qr = lane >> 2, qc = lane & 3;
    const unsigned* Ah = hhiu + (mi * 16 + qr) * RWP + qc + kseg * 128;
    const unsigned* Al = hlou + (mi * 16 + qr) * RWP + qc + kseg * 128;
    const unsigned* Bh = whiu + (ni * 8 + qr) * RWP + qc + kseg * 128;
    const unsigned* Bl = wlou + (ni * 8 + qr) * RWP + qc + kseg * 128;
    float* csw = kseg ? cs1 : cs0;

    for (int s = 0; s < Tlen; ++s) {
        const int tcur = dir ? (Tlen - 1 - s) : s;

        if (s > 0) {
            const int tprev = dir ? (tcur + 1) : (tcur - 1);
            const int lb = tid >> 4;             // 0..31 batch
            const int q  = tid & 15;             // uint4 slot
            const uint4* ph = (const uint4*)(shi + ((size_t)tprev * Bsz + lb) * 512);
            const uint4* pl = (const uint4*)(slo + ((size_t)tprev * Bsz + lb) * 512);
#pragma unroll
            for (int it = 0; it < 4; ++it) {
                uint4 vh = ph[q + it * 16];
                uint4 vl = pl[q + it * 16];
                *(uint4*)&hhiu[lb * RWP + q * 4 + it * 64] = vh;
                *(uint4*)&hlou[lb * RWP + q * 4 + it * 64] = vl;
            }
        }
        __syncthreads();

        float cc[4] = {0.f, 0.f, 0.f, 0.f};
#pragma unroll 4
        for (int kt = 0; kt < 16; ++kt) {
            const int o = kt * 8;
            unsigned ah[4], al[4], bh[2], bl[2];
            ah[0] = Ah[o];            ah[1] = Ah[o + 8 * RWP];
            ah[2] = Ah[o + 4];        ah[3] = Ah[o + 8 * RWP + 4];
            al[0] = Al[o];            al[1] = Al[o + 8 * RWP];
            al[2] = Al[o + 4];        al[3] = Al[o + 8 * RWP + 4];
            bh[0] = Bh[o];            bh[1] = Bh[o + 4];
            bl[0] = Bl[o];            bl[1] = Bl[o + 4];
            mma_bf16(cc, ah, bh);
            mma_bf16(cc, ah, bl);
            mma_bf16(cc, al, bh);
        }
        {
            int r0 = mi * 16 + qr;
            int nc = ni * 8 + 2 * qc;
            csw[r0 * 33 + nc]           = cc[0];
            csw[r0 * 33 + nc + 1]       = cc[1];
            csw[(r0 + 8) * 33 + nc]     = cc[2];
            csw[(r0 + 8) * 33 + nc + 1] = cc[3];
        }
        __syncthreads();

        if (tid < 256) {
            int base = eb * 33 + (tid & 7) * 4;
            float gi = cs0[base + 0] + cs1[base + 0] + pxi;
            float gf = cs0[base + 1] + cs1[base + 1] + pxf;
            float gg = cs0[base + 2] + cs1[base + 2] + pxg;
            float go = cs0[base + 3] + cs1[base + 3] + pxo;
            cstate = sigmoidf(gf) * cstate + sigmoidf(gi) * tanhf(gg);
            float h = sigmoidf(go) * tanhf(cstate);
            seq[(size_t)(eb * Tlen + tcur) * 1024 + dir * 512 + ej] = h;
            hsum += h;
            unsigned short hh, hl;
            split_bf16(h, hh, hl);
            size_t si = ((size_t)tcur * Bsz + eb) * 512 + ej;
            shi[si] = hh;
            slo[si] = hl;
        }

        if (s + 1 < Tlen) {
            if (tid < 256) {
                int tn = dir ? (tcur - 1) : (tcur + 1);
                int bs = (eb * Tlen + tn) * 2048;
                pxi = xg[bs + ej];        pxf = xg[bs + 512 + ej];
                pxg = xg[bs + 1024 + ej]; pxo = xg[bs + 1536 + ej];
            }
            target += nb;
            grid_sync(sync_cnt, target);
        }
    }

    if (avg && tid < 256) avg[eb * 1024 + dir * 512 + ej] = hsum * (1.f / Tlen);
}

// ---------------- launch ------------------------------------------------------
extern "C" void kernel_launch(void* const* d_in, const int* in_sizes, int n_in,
                              void* d_out, int out_size)
{
    const float* x     = (const float*)d_in[0];
    const float* Wih0f = (const float*)d_in[1];
    const float* Whh0f = (const float*)d_in[2];
    const float* b0f   = (const float*)d_in[3];
    const float* Wih0b = (const float*)d_in[4];
    const float* Whh0b = (const float*)d_in[5];
    const float* b0b   = (const float*)d_in[6];
    const float* Wih1f = (const float*)d_in[7];
    const float* Whh1f = (const float*)d_in[8];
    const float* b1f   = (const float*)d_in[9];
    const float* Wih1b = (const float*)d_in[10];
    const float* Whh1b = (const float*)d_in[11];
    const float* b1b   = (const float*)d_in[12];

    float* avg    = (float*)d_out;
    float* outseq = avg + Bsz * 2 * Hd;   // avg_out first, then out [B,T,1024]

    float *xg0, *xg1, *x1;
    unsigned int* syncp;
    cudaGetSymbolAddress((void**)&xg0, g_xg0);
    cudaGetSymbolAddress((void**)&xg1, g_xg1);
    cudaGetSymbolAddress((void**)&x1,  g_x1);
    cudaGetSymbolAddress((void**)&syncp, g_sync);

    cudaFuncSetAttribute(lstm_persist, cudaFuncAttributeMaxDynamicSharedMemorySize, LSTM_SMEM);
    cudaFuncSetAttribute(bf16_gemm_bias, cudaFuncAttributeMaxDynamicSharedMemorySize, GEMM_SMEM);

    dim3 gemm_grid(2048 / 128, 16384 / 128);     // (16, 128)
    dim3 step_grid(64, 2);

    reset_sync<<<1, 1>>>(syncp);

    // Layer 0 input gates (bf16 3-term split, 512-thread tensor-core GEMM)
    bf16_gemm_bias<<<gemm_grid, 512, GEMM_SMEM>>>(x, Wih0f, b0f, xg0, 16384, 2048, 512);
    bf16_gemm_bias<<<gemm_grid, 512, GEMM_SMEM>>>(x, Wih0b, b0b, xg1, 16384, 2048, 512);
    // Layer 0 recurrence (persistent bf16 tensor-core, counters 0,1)
    lstm_persist<<<step_grid, 512, LSTM_SMEM>>>(xg0, xg1, Whh0f, Whh0b, x1, nullptr, syncp);
    // Layer 1 input gates (K = 1024)
    bf16_gemm_bias<<<gemm_grid, 512, GEMM_SMEM>>>(x1, Wih1f, b1f, xg0, 16384, 2048, 1024);
    bf16_gemm_bias<<<gemm_grid, 512, GEMM_SMEM>>>(x1, Wih1b, b1b, xg1, 16384, 2048, 1024);
    // Layer 1 recurrence -> out region of d_out, mean fused (counters 2,3)
    lstm_persist<<<step_grid, 512, LSTM_SMEM>>>(xg0, xg1, Whh1f, Whh1b, outseq, avg, syncp + 2);
}